// round 1
// baseline (speedup 1.0000x reference)
#include <cuda_runtime.h>
#include <math.h>

// ---------------- problem constants (fixed by the dataset) ----------------
#define BS 8
#define NQ 900
#define DM 256
#define NH 8
#define NL 3
#define NP 4
#define DH 32                 // DM / NH
#define SUMHW 21504           // 128*128 + 64*64 + 32*32
#define NOFF (NH*NL*NP*2)     // 192
#define NATT (NH*NL*NP)       // 96

// ---------------- scratch (device globals; no allocations) ----------------
__device__ float g_value[(size_t)BS * SUMHW * DM];   // 176 MB
__device__ float g_off[(size_t)BS * NQ * NOFF];
__device__ float g_att[(size_t)BS * NQ * NATT];
__device__ float g_acc[(size_t)BS * NQ * DM];

// ---------------- generic fp32 SGEMM: C = A(MxK) @ B(KxN) + bias ----------
// BM=128, BN=128, BK=8, 256 threads, 8x8 per thread.
__global__ __launch_bounds__(256) void sgemm128(
    const float* __restrict__ A, const float* __restrict__ B,
    const float* __restrict__ bias, float* __restrict__ C,
    int M, int N, int K)
{
    __shared__ float As[8][128];
    __shared__ float Bs[8][128];

    const int tid = threadIdx.x;
    const int bm = blockIdx.y * 128;
    const int bn = blockIdx.x * 128;

    // A loader: 128 rows x 8 k, one float4 per thread
    const int aRow = tid >> 1;          // 0..127
    const int aK   = (tid & 1) * 4;     // 0 or 4
    // B loader: 8 rows x 128 cols, one float4 per thread
    const int bRow = tid >> 5;          // 0..7
    const int bCol = (tid & 31) * 4;    // 0..124

    const int tx = tid & 15;            // 0..15 -> 8 cols each
    const int ty = tid >> 4;            // 0..15 -> 8 rows each

    float acc[8][8];
#pragma unroll
    for (int i = 0; i < 8; i++)
#pragma unroll
        for (int j = 0; j < 8; j++) acc[i][j] = 0.f;

    for (int k0 = 0; k0 < K; k0 += 8) {
        // ---- load A tile (transposed into As[k][row]) ----
        float4 a4 = make_float4(0.f, 0.f, 0.f, 0.f);
        const int gr = bm + aRow;
        if (gr < M)
            a4 = *reinterpret_cast<const float4*>(A + (size_t)gr * K + k0 + aK);
        As[aK + 0][aRow] = a4.x;
        As[aK + 1][aRow] = a4.y;
        As[aK + 2][aRow] = a4.z;
        As[aK + 3][aRow] = a4.w;

        // ---- load B tile ----  (N is always a multiple of 4 here)
        float4 b4 = make_float4(0.f, 0.f, 0.f, 0.f);
        const int gc = bn + bCol;
        if (gc < N)
            b4 = *reinterpret_cast<const float4*>(B + (size_t)(k0 + bRow) * N + gc);
        *reinterpret_cast<float4*>(&Bs[bRow][bCol]) = b4;

        __syncthreads();

#pragma unroll
        for (int k = 0; k < 8; k++) {
            float4 a0 = *reinterpret_cast<const float4*>(&As[k][ty * 8 + 0]);
            float4 a1 = *reinterpret_cast<const float4*>(&As[k][ty * 8 + 4]);
            float4 b0 = *reinterpret_cast<const float4*>(&Bs[k][tx * 8 + 0]);
            float4 b1 = *reinterpret_cast<const float4*>(&Bs[k][tx * 8 + 4]);
            const float ar[8] = {a0.x, a0.y, a0.z, a0.w, a1.x, a1.y, a1.z, a1.w};
            const float br[8] = {b0.x, b0.y, b0.z, b0.w, b1.x, b1.y, b1.z, b1.w};
#pragma unroll
            for (int i = 0; i < 8; i++)
#pragma unroll
                for (int j = 0; j < 8; j++)
                    acc[i][j] = fmaf(ar[i], br[j], acc[i][j]);
        }
        __syncthreads();
    }

    // ---- epilogue: bias + guarded store ----
#pragma unroll
    for (int i = 0; i < 8; i++) {
        const int row = bm + ty * 8 + i;
        if (row >= M) continue;
#pragma unroll
        for (int j = 0; j < 8; j++) {
            const int col = bn + tx * 8 + j;
            if (col < N)
                C[(size_t)row * N + col] = acc[i][j] + bias[col];
        }
    }
}

// ---------------- sampling: one warp per (b, q, h) ------------------------
__global__ __launch_bounds__(256) void msda_sample(
    const float* __restrict__ refp_g,   // [BS, NQ, NL, 2]
    const float* __restrict__ off_g,    // [BS, NQ, NOFF]
    const float* __restrict__ att_g,    // [BS, NQ, NATT]
    const float* __restrict__ value_g,  // [BS, SUMHW, DM]
    float* __restrict__ acc_g)          // [BS, NQ, DM]
{
    const int gwarp = (blockIdx.x * blockDim.x + threadIdx.x) >> 5;
    const int lane  = threadIdx.x & 31;
    if (gwarp >= BS * NQ * NH) return;

    const int h  = gwarp & (NH - 1);
    const int bq = gwarp >> 3;          // b*NQ + q
    const int b  = bq / NQ;

    // softmax over the 12 logits of this head (broadcast loads)
    const float* att = att_g + (size_t)bq * NATT + h * (NL * NP);
    float w[NL * NP];
    float mx = -INFINITY;
#pragma unroll
    for (int i = 0; i < NL * NP; i++) { w[i] = att[i]; mx = fmaxf(mx, w[i]); }
    float sum = 0.f;
#pragma unroll
    for (int i = 0; i < NL * NP; i++) { w[i] = expf(w[i] - mx); sum += w[i]; }
    const float inv = 1.f / sum;
#pragma unroll
    for (int i = 0; i < NL * NP; i++) w[i] *= inv;

    const float* off = off_g + (size_t)bq * NOFF + h * (NL * NP * 2);
    const float* rp  = refp_g + (size_t)bq * (NL * 2);

    const int d = h * DH + lane;
    const float* vb = value_g + (size_t)b * SUMHW * DM + d;

    const int Hs[NL] = {128, 64, 32};
    const int Ws[NL] = {128, 64, 32};
    const int St[NL] = {0, 16384, 20480};

    float a = 0.f;
#pragma unroll
    for (int l = 0; l < NL; l++) {
        const int Wl = Ws[l], Hl = Hs[l], st = St[l];
        const float rx = rp[l * 2 + 0] * (float)Wl;
        const float ry = rp[l * 2 + 1] * (float)Hl;
#pragma unroll
        for (int p = 0; p < NP; p++) {
            const float px = rx + off[l * (NP * 2) + p * 2 + 0] - 0.5f;
            const float py = ry + off[l * (NP * 2) + p * 2 + 1] - 0.5f;
            const float fx = floorf(px), fy = floorf(py);
            const float lx = px - fx, ly = py - fy;
            const int x0 = (int)fx, y0 = (int)fy;
            const float aw = w[l * NP + p];

            const float w00 = (1.f - lx) * (1.f - ly);
            const float w10 = lx * (1.f - ly);
            const float w01 = (1.f - lx) * ly;
            const float w11 = lx * ly;

            float s = 0.f;
            if (x0 >= 0 && x0 < Wl && y0 >= 0 && y0 < Hl)
                s = fmaf(w00, vb[(size_t)(st + y0 * Wl + x0) * DM], s);
            if (x0 + 1 >= 0 && x0 + 1 < Wl && y0 >= 0 && y0 < Hl)
                s = fmaf(w10, vb[(size_t)(st + y0 * Wl + x0 + 1) * DM], s);
            if (x0 >= 0 && x0 < Wl && y0 + 1 >= 0 && y0 + 1 < Hl)
                s = fmaf(w01, vb[(size_t)(st + (y0 + 1) * Wl + x0) * DM], s);
            if (x0 + 1 >= 0 && x0 + 1 < Wl && y0 + 1 >= 0 && y0 + 1 < Hl)
                s = fmaf(w11, vb[(size_t)(st + (y0 + 1) * Wl + x0 + 1) * DM], s);
            a = fmaf(aw, s, a);
        }
    }
    acc_g[(size_t)bq * DM + d] = a;
}

// ---------------- launch ---------------------------------------------------
extern "C" void kernel_launch(void* const* d_in, const int* in_sizes, int n_in,
                              void* d_out, int out_size)
{
    const float* query  = (const float*)d_in[0];
    const float* refpts = (const float*)d_in[1];
    const float* inflat = (const float*)d_in[2];
    // d_in[3] spatial_shapes, d_in[4] level_start_index: constants, hardcoded
    const float* W_off  = (const float*)d_in[5];
    const float* b_off  = (const float*)d_in[6];
    const float* W_attn = (const float*)d_in[7];
    const float* b_attn = (const float*)d_in[8];
    const float* W_val  = (const float*)d_in[9];
    const float* b_val  = (const float*)d_in[10];
    const float* W_out  = (const float*)d_in[11];
    const float* b_out  = (const float*)d_in[12];
    float* out = (float*)d_out;

    float *value, *off, *att, *acc;
    cudaGetSymbolAddress((void**)&value, g_value);
    cudaGetSymbolAddress((void**)&off,   g_off);
    cudaGetSymbolAddress((void**)&att,   g_att);
    cudaGetSymbolAddress((void**)&acc,   g_acc);

    const int MQ = BS * NQ;          // 7200
    const int MV = BS * SUMHW;       // 172032

    // offsets projection: [7200,256] @ [256,192]
    sgemm128<<<dim3((NOFF + 127) / 128, (MQ + 127) / 128), 256>>>(
        query, W_off, b_off, off, MQ, NOFF, DM);
    // attention projection: [7200,256] @ [256,96]
    sgemm128<<<dim3((NATT + 127) / 128, (MQ + 127) / 128), 256>>>(
        query, W_attn, b_attn, att, MQ, NATT, DM);
    // value projection: [172032,256] @ [256,256]
    sgemm128<<<dim3(DM / 128, MV / 128), 256>>>(
        inflat, W_val, b_val, value, MV, DM, DM);
    // bilinear sampling + attention-weighted accumulation
    {
        const int warps = BS * NQ * NH;             // 57600
        const int threads = 256;
        const int blocks = (warps * 32 + threads - 1) / threads;
        msda_sample<<<blocks, threads>>>(refpts, off, att, value, acc);
    }
    // output projection: [7200,256] @ [256,256] -> d_out
    sgemm128<<<dim3(DM / 128, (MQ + 127) / 128), 256>>>(
        acc, W_out, b_out, out, MQ, DM, DM);
}

// round 2
// speedup vs baseline: 2.0246x; 2.0246x over previous
#include <cuda_runtime.h>
#include <math.h>

// ---------------- problem constants (fixed by the dataset) ----------------
#define BS 8
#define NQ 900
#define DM 256
#define NH 8
#define NL 3
#define NP 4
#define DH 32                 // DM / NH
#define SUMHW 21504           // 128*128 + 64*64 + 32*32
#define NOFF (NH*NL*NP*2)     // 192
#define NATT (NH*NL*NP)       // 96

// ---------------- scratch (device globals; no allocations) ----------------
__device__ float g_value[(size_t)BS * SUMHW * DM];   // 176 MB
__device__ float g_off[(size_t)BS * NQ * NOFF];
__device__ float g_att[(size_t)BS * NQ * NATT];
__device__ float g_acc[(size_t)BS * NQ * DM];

// ================= TF32 tensor-core GEMM (exact-tile version) =============
// C[M,N] = A[M,K] @ B[K,N] + bias.  Requires M%128==0, N%128==0, K%32==0.
// BM=128, BN=128, BK=32, 256 threads = 8 warps, warp tile 32x64.
// cp.async double-buffered smem, XOR-swizzled (conflict-free frag LDS).

__device__ __forceinline__ void cp16(unsigned dst, const void* src) {
    asm volatile("cp.async.cg.shared.global [%0], [%1], 16;\n" :: "r"(dst), "l"(src));
}
__device__ __forceinline__ unsigned tf32r(float x) {
    unsigned u;
    asm("cvt.rna.tf32.f32 %0, %1;\n" : "=r"(u) : "f"(x));
    return u;
}
__device__ __forceinline__ void mma_tf32(float c[4], const unsigned a[4],
                                         unsigned b0, unsigned b1) {
    asm volatile(
        "mma.sync.aligned.m16n8k8.row.col.f32.tf32.tf32.f32 "
        "{%0,%1,%2,%3}, {%4,%5,%6,%7}, {%8,%9}, {%0,%1,%2,%3};\n"
        : "+f"(c[0]), "+f"(c[1]), "+f"(c[2]), "+f"(c[3])
        : "r"(a[0]), "r"(a[1]), "r"(a[2]), "r"(a[3]), "r"(b0), "r"(b1));
}

// smem index helpers (float units)
__device__ __forceinline__ int asw(int m, int k) { return m * 32 + (k ^ ((m & 7) << 2)); }
__device__ __forceinline__ int bsw(int k, int n) { return k * 128 + (n ^ ((k & 3) << 3)); }

__global__ __launch_bounds__(256, 2) void gemm_tf32(
    const float* __restrict__ A, const float* __restrict__ B,
    const float* __restrict__ bias, float* __restrict__ C,
    int M, int N, int K)
{
    extern __shared__ float sm[];
    float* As = sm;          // [2][128*32]
    float* Bs = sm + 8192;   // [2][32*128]

    const int tid = threadIdx.x;
    const int wid = tid >> 5;
    const int lane = tid & 31;
    const int g  = lane >> 2;   // groupID 0..7
    const int t4 = lane & 3;    // 0..3

    const int bm = blockIdx.y * 128;
    const int bn = blockIdx.x * 128;
    const int warp_m = (wid >> 1) * 32;   // 0,32,64,96
    const int warp_n = (wid & 1) * 64;    // 0,64

    const unsigned smA = (unsigned)__cvta_generic_to_shared(As);
    const unsigned smB = (unsigned)__cvta_generic_to_shared(Bs);

    float c[2][8][4];
#pragma unroll
    for (int mi = 0; mi < 2; mi++)
#pragma unroll
        for (int nj = 0; nj < 8; nj++)
#pragma unroll
            for (int r = 0; r < 4; r++) c[mi][nj][r] = 0.f;

    const int nT = K / 32;

    // ---- stage loader ----
    auto load_stage = [&](int t, int s) {
        const float* Ag = A + (size_t)bm * K + t * 32;
#pragma unroll
        for (int p = 0; p < 4; p++) {
            int ci = p * 256 + tid;
            int m = ci >> 3, k4 = (ci & 7) << 2;
            cp16(smA + (unsigned)(s * 4096 + asw(m, k4)) * 4u,
                 Ag + (size_t)m * K + k4);
        }
        const float* Bg = B + (size_t)(t * 32) * N + bn;
#pragma unroll
        for (int p = 0; p < 4; p++) {
            int ci = p * 256 + tid;
            int k = ci >> 5, n4 = (ci & 31) << 2;
            cp16(smB + (unsigned)(s * 4096 + bsw(k, n4)) * 4u,
                 Bg + (size_t)k * N + n4);
        }
    };

    load_stage(0, 0);
    asm volatile("cp.async.commit_group;\n");

    for (int t = 0; t < nT; t++) {
        if (t + 1 < nT) {
            load_stage(t + 1, (t + 1) & 1);
            asm volatile("cp.async.commit_group;\n");
            asm volatile("cp.async.wait_group 1;\n");
        } else {
            asm volatile("cp.async.wait_group 0;\n");
        }
        __syncthreads();

        const float* as = As + (t & 1) * 4096;
        const float* bs = Bs + (t & 1) * 4096;

#pragma unroll
        for (int kk = 0; kk < 32; kk += 8) {
            const int kA = kk + t4;
            unsigned a[2][4];
#pragma unroll
            for (int mi = 0; mi < 2; mi++) {
                const int r0 = warp_m + mi * 16 + g;
                const int r1 = r0 + 8;
                a[mi][0] = tf32r(as[asw(r0, kA)]);
                a[mi][1] = tf32r(as[asw(r1, kA)]);
                a[mi][2] = tf32r(as[asw(r0, kA + 4)]);
                a[mi][3] = tf32r(as[asw(r1, kA + 4)]);
            }
#pragma unroll
            for (int nj = 0; nj < 8; nj++) {
                const int col = warp_n + nj * 8 + g;
                unsigned b0 = tf32r(bs[bsw(kA, col)]);
                unsigned b1 = tf32r(bs[bsw(kA + 4, col)]);
                mma_tf32(c[0][nj], a[0], b0, b1);
                mma_tf32(c[1][nj], a[1], b0, b1);
            }
        }
        __syncthreads();
    }

    // ---- epilogue: bias + store (float2) ----
#pragma unroll
    for (int mi = 0; mi < 2; mi++) {
        const int r0 = bm + warp_m + mi * 16 + g;
#pragma unroll
        for (int nj = 0; nj < 8; nj++) {
            const int col = bn + warp_n + nj * 8 + 2 * t4;
            const float bx = bias[col], by = bias[col + 1];
            float2 v0 = make_float2(c[mi][nj][0] + bx, c[mi][nj][1] + by);
            float2 v1 = make_float2(c[mi][nj][2] + bx, c[mi][nj][3] + by);
            *reinterpret_cast<float2*>(C + (size_t)r0 * N + col) = v0;
            *reinterpret_cast<float2*>(C + (size_t)(r0 + 8) * N + col) = v1;
        }
    }
}

// ---------------- generic fp32 SGEMM (small/q-side GEMMs) -----------------
__global__ __launch_bounds__(256) void sgemm128(
    const float* __restrict__ A, const float* __restrict__ B,
    const float* __restrict__ bias, float* __restrict__ C,
    int M, int N, int K)
{
    __shared__ float As[8][128];
    __shared__ float Bs[8][128];

    const int tid = threadIdx.x;
    const int bm = blockIdx.y * 128;
    const int bn = blockIdx.x * 128;

    const int aRow = tid >> 1;
    const int aK   = (tid & 1) * 4;
    const int bRow = tid >> 5;
    const int bCol = (tid & 31) * 4;

    const int tx = tid & 15;
    const int ty = tid >> 4;

    float acc[8][8];
#pragma unroll
    for (int i = 0; i < 8; i++)
#pragma unroll
        for (int j = 0; j < 8; j++) acc[i][j] = 0.f;

    for (int k0 = 0; k0 < K; k0 += 8) {
        float4 a4 = make_float4(0.f, 0.f, 0.f, 0.f);
        const int gr = bm + aRow;
        if (gr < M)
            a4 = *reinterpret_cast<const float4*>(A + (size_t)gr * K + k0 + aK);
        As[aK + 0][aRow] = a4.x;
        As[aK + 1][aRow] = a4.y;
        As[aK + 2][aRow] = a4.z;
        As[aK + 3][aRow] = a4.w;

        float4 b4 = make_float4(0.f, 0.f, 0.f, 0.f);
        const int gc = bn + bCol;
        if (gc < N)
            b4 = *reinterpret_cast<const float4*>(B + (size_t)(k0 + bRow) * N + gc);
        *reinterpret_cast<float4*>(&Bs[bRow][bCol]) = b4;

        __syncthreads();

#pragma unroll
        for (int k = 0; k < 8; k++) {
            float4 a0 = *reinterpret_cast<const float4*>(&As[k][ty * 8 + 0]);
            float4 a1 = *reinterpret_cast<const float4*>(&As[k][ty * 8 + 4]);
            float4 b0 = *reinterpret_cast<const float4*>(&Bs[k][tx * 8 + 0]);
            float4 b1 = *reinterpret_cast<const float4*>(&Bs[k][tx * 8 + 4]);
            const float ar[8] = {a0.x, a0.y, a0.z, a0.w, a1.x, a1.y, a1.z, a1.w};
            const float br[8] = {b0.x, b0.y, b0.z, b0.w, b1.x, b1.y, b1.z, b1.w};
#pragma unroll
            for (int i = 0; i < 8; i++)
#pragma unroll
                for (int j = 0; j < 8; j++)
                    acc[i][j] = fmaf(ar[i], br[j], acc[i][j]);
        }
        __syncthreads();
    }

#pragma unroll
    for (int i = 0; i < 8; i++) {
        const int row = bm + ty * 8 + i;
        if (row >= M) continue;
#pragma unroll
        for (int j = 0; j < 8; j++) {
            const int col = bn + tx * 8 + j;
            if (col < N)
                C[(size_t)row * N + col] = acc[i][j] + bias[col];
        }
    }
}

// ---------------- sampling: one warp per (b, q, h) ------------------------
__global__ __launch_bounds__(256) void msda_sample(
    const float* __restrict__ refp_g,   // [BS, NQ, NL, 2]
    const float* __restrict__ off_g,    // [BS, NQ, NOFF]
    const float* __restrict__ att_g,    // [BS, NQ, NATT]
    const float* __restrict__ value_g,  // [BS, SUMHW, DM]
    float* __restrict__ acc_g)          // [BS, NQ, DM]
{
    const int gwarp = (blockIdx.x * blockDim.x + threadIdx.x) >> 5;
    const int lane  = threadIdx.x & 31;
    if (gwarp >= BS * NQ * NH) return;

    const int h  = gwarp & (NH - 1);
    const int bq = gwarp >> 3;
    const int b  = bq / NQ;

    const float* att = att_g + (size_t)bq * NATT + h * (NL * NP);
    float w[NL * NP];
    float mx = -INFINITY;
#pragma unroll
    for (int i = 0; i < NL * NP; i++) { w[i] = att[i]; mx = fmaxf(mx, w[i]); }
    float sum = 0.f;
#pragma unroll
    for (int i = 0; i < NL * NP; i++) { w[i] = expf(w[i] - mx); sum += w[i]; }
    const float inv = 1.f / sum;
#pragma unroll
    for (int i = 0; i < NL * NP; i++) w[i] *= inv;

    const float* off = off_g + (size_t)bq * NOFF + h * (NL * NP * 2);
    const float* rp  = refp_g + (size_t)bq * (NL * 2);

    const int d = h * DH + lane;
    const float* vb = value_g + (size_t)b * SUMHW * DM + d;

    const int Hs[NL] = {128, 64, 32};
    const int Ws[NL] = {128, 64, 32};
    const int St[NL] = {0, 16384, 20480};

    float a = 0.f;
#pragma unroll
    for (int l = 0; l < NL; l++) {
        const int Wl = Ws[l], Hl = Hs[l], st = St[l];
        const float rx = rp[l * 2 + 0] * (float)Wl;
        const float ry = rp[l * 2 + 1] * (float)Hl;
#pragma unroll
        for (int p = 0; p < NP; p++) {
            const float px = rx + off[l * (NP * 2) + p * 2 + 0] - 0.5f;
            const float py = ry + off[l * (NP * 2) + p * 2 + 1] - 0.5f;
            const float fx = floorf(px), fy = floorf(py);
            const float lx = px - fx, ly = py - fy;
            const int x0 = (int)fx, y0 = (int)fy;
            const float aw = w[l * NP + p];

            const float w00 = (1.f - lx) * (1.f - ly);
            const float w10 = lx * (1.f - ly);
            const float w01 = (1.f - lx) * ly;
            const float w11 = lx * ly;

            float s = 0.f;
            if (x0 >= 0 && x0 < Wl && y0 >= 0 && y0 < Hl)
                s = fmaf(w00, vb[(size_t)(st + y0 * Wl + x0) * DM], s);
            if (x0 + 1 >= 0 && x0 + 1 < Wl && y0 >= 0 && y0 < Hl)
                s = fmaf(w10, vb[(size_t)(st + y0 * Wl + x0 + 1) * DM], s);
            if (x0 >= 0 && x0 < Wl && y0 + 1 >= 0 && y0 + 1 < Hl)
                s = fmaf(w01, vb[(size_t)(st + (y0 + 1) * Wl + x0) * DM], s);
            if (x0 + 1 >= 0 && x0 + 1 < Wl && y0 + 1 >= 0 && y0 + 1 < Hl)
                s = fmaf(w11, vb[(size_t)(st + (y0 + 1) * Wl + x0 + 1) * DM], s);
            a = fmaf(aw, s, a);
        }
    }
    acc_g[(size_t)bq * DM + d] = a;
}

// ---------------- launch ---------------------------------------------------
extern "C" void kernel_launch(void* const* d_in, const int* in_sizes, int n_in,
                              void* d_out, int out_size)
{
    const float* query  = (const float*)d_in[0];
    const float* refpts = (const float*)d_in[1];
    const float* inflat = (const float*)d_in[2];
    const float* W_off  = (const float*)d_in[5];
    const float* b_off  = (const float*)d_in[6];
    const float* W_attn = (const float*)d_in[7];
    const float* b_attn = (const float*)d_in[8];
    const float* W_val  = (const float*)d_in[9];
    const float* b_val  = (const float*)d_in[10];
    const float* W_out  = (const float*)d_in[11];
    const float* b_out  = (const float*)d_in[12];
    float* out = (float*)d_out;

    float *value, *off, *att, *acc;
    cudaGetSymbolAddress((void**)&value, g_value);
    cudaGetSymbolAddress((void**)&off,   g_off);
    cudaGetSymbolAddress((void**)&att,   g_att);
    cudaGetSymbolAddress((void**)&acc,   g_acc);

    const int MQ = BS * NQ;          // 7200
    const int MV = BS * SUMHW;       // 172032

    // offsets projection: [7200,256] @ [256,192]
    sgemm128<<<dim3((NOFF + 127) / 128, (MQ + 127) / 128), 256>>>(
        query, W_off, b_off, off, MQ, NOFF, DM);
    // attention projection: [7200,256] @ [256,96]
    sgemm128<<<dim3((NATT + 127) / 128, (MQ + 127) / 128), 256>>>(
        query, W_attn, b_attn, att, MQ, NATT, DM);
    // value projection (TF32 tensor cores): [172032,256] @ [256,256]
    {
        const int smem = 2 * (128 * 32 + 32 * 128) * (int)sizeof(float);  // 64 KB
        cudaFuncSetAttribute(gemm_tf32, cudaFuncAttributeMaxDynamicSharedMemorySize, smem);
        gemm_tf32<<<dim3(DM / 128, MV / 128), 256, smem>>>(
            inflat, W_val, b_val, value, MV, DM, DM);
    }
    // bilinear sampling + attention-weighted accumulation
    {
        const int warps = BS * NQ * NH;             // 57600
        const int threads = 256;
        const int blocks = (warps * 32 + threads - 1) / threads;
        msda_sample<<<blocks, threads>>>(refpts, off, att, value, acc);
    }
    // output projection: [7200,256] @ [256,256] -> d_out
    sgemm128<<<dim3(DM / 128, (MQ + 127) / 128), 256>>>(
        acc, W_out, b_out, out, MQ, DM, DM);
}

// round 4
// speedup vs baseline: 2.6678x; 1.3177x over previous
#include <cuda_runtime.h>
#include <math.h>

// ---------------- problem constants ----------------
#define BS 8
#define NQ 900
#define DM 256
#define NH 8
#define NL 3
#define NP 4
#define DH 32
#define SUMHW 21504           // 128*128 + 64*64 + 32*32
#define NOFF 192              // NH*NL*NP*2
#define NATT 96               // NH*NL*NP
#define QS  (NOFF + NATT)     // 288

// ---------------- scratch ----------------
__device__ float g_value[(size_t)BS * SUMHW * DM];   // 176 MB
__device__ float g_qproj[(size_t)BS * NQ * QS];      // 8.3 MB
__device__ float g_acc[(size_t)BS * NQ * DM];
__device__ float g_wcat[DM * QS];
__device__ float g_bcat[QS];

// ---------------- ptx helpers ----------------
__device__ __forceinline__ void cp16(unsigned dst, const void* src) {
    asm volatile("cp.async.cg.shared.global [%0], [%1], 16;\n" :: "r"(dst), "l"(src));
}
__device__ __forceinline__ float tf32f(float x) {
    unsigned u;
    asm("cvt.rna.tf32.f32 %0, %1;\n" : "=r"(u) : "f"(x));
    return __uint_as_float(u);
}
__device__ __forceinline__ void mma_tf32(float c[4], const unsigned a[4],
                                         unsigned b0, unsigned b1) {
    asm volatile(
        "mma.sync.aligned.m16n8k8.row.col.f32.tf32.tf32.f32 "
        "{%0,%1,%2,%3}, {%4,%5,%6,%7}, {%8,%9}, {%0,%1,%2,%3};\n"
        : "+f"(c[0]), "+f"(c[1]), "+f"(c[2]), "+f"(c[3])
        : "r"(a[0]), "r"(a[1]), "r"(a[2]), "r"(a[3]), "r"(b0), "r"(b1));
}

// smem swizzles (float units) — conflict-free for both STS and frag LDS
__device__ __forceinline__ int asw(int m, int k)    { return m * 32  + (k ^ ((m & 7) << 2)); }
__device__ __forceinline__ int bsw128(int k, int n) { return k * 128 + (n ^ ((k & 3) << 3)); }
__device__ __forceinline__ int bsw256(int k, int n) { return k * 256 + (n ^ ((k & 3) << 3)); }

// in-place tf32 round of a float4 in smem
__device__ __forceinline__ void cvt4(float* p) {
    float4 v = *reinterpret_cast<float4*>(p);
    v.x = tf32f(v.x); v.y = tf32f(v.y); v.z = tf32f(v.z); v.w = tf32f(v.w);
    *reinterpret_cast<float4*>(p) = v;
}

// ============ value GEMM: C[M,256] = A[M,256] @ B[256,256] + bias ==========
// BM=128, BN=256, BK=32, 512 threads = 16 warps, warp tile 32x64.
// M % 128 == 0.  cp.async double buffer; bulk tf32 cvt pass per stage.
__global__ __launch_bounds__(512, 1) void gemm_tf32_val(
    const float* __restrict__ A, const float* __restrict__ B,
    const float* __restrict__ bias, float* __restrict__ C)
{
    extern __shared__ float sm[];
    float* As = sm;           // [2][4096]
    float* Bs = sm + 8192;    // [2][8192]

    const int tid = threadIdx.x;
    const int wid = tid >> 5, lane = tid & 31;
    const int g = lane >> 2, t4 = lane & 3;
    const int bm = blockIdx.x * 128;
    const int warp_m = (wid >> 2) * 32;   // 0,32,64,96
    const int warp_n = (wid & 3) * 64;    // 0,64,128,192

    const unsigned smA = (unsigned)__cvta_generic_to_shared(As);
    const unsigned smB = (unsigned)__cvta_generic_to_shared(Bs);

    float c[2][8][4];
#pragma unroll
    for (int mi = 0; mi < 2; mi++)
#pragma unroll
        for (int nj = 0; nj < 8; nj++)
#pragma unroll
            for (int r = 0; r < 4; r++) c[mi][nj][r] = 0.f;

    auto load_stage = [&](int t, int s) {
        const float* Ag = A + (size_t)bm * 256 + t * 32;
#pragma unroll
        for (int p = 0; p < 2; p++) {
            int ci = p * 512 + tid;
            int m = ci >> 3, k4 = (ci & 7) << 2;
            cp16(smA + (unsigned)(s * 4096 + asw(m, k4)) * 4u, Ag + (size_t)m * 256 + k4);
        }
        const float* Bg = B + (size_t)(t * 32) * 256;
#pragma unroll
        for (int p = 0; p < 4; p++) {
            int ci = p * 512 + tid;
            int k = ci >> 6, n4 = (ci & 63) << 2;
            cp16(smB + (unsigned)(s * 8192 + bsw256(k, n4)) * 4u, Bg + (size_t)k * 256 + n4);
        }
    };

    load_stage(0, 0);
    asm volatile("cp.async.commit_group;\n");

#pragma unroll 1
    for (int t = 0; t < 8; t++) {
        if (t + 1 < 8) {
            load_stage(t + 1, (t + 1) & 1);
            asm volatile("cp.async.commit_group;\n");
            asm volatile("cp.async.wait_group 1;\n");
        } else {
            asm volatile("cp.async.wait_group 0;\n");
        }
        __syncthreads();

        float* as = As + (t & 1) * 4096;
        float* bs = Bs + (t & 1) * 8192;

        // bulk tf32 rounding pass (out of the MMA chain)
#pragma unroll
        for (int p = 0; p < 2; p++) cvt4(as + (p * 512 + tid) * 4);
#pragma unroll
        for (int p = 0; p < 4; p++) cvt4(bs + (p * 512 + tid) * 4);
        __syncthreads();

#pragma unroll
        for (int kk = 0; kk < 32; kk += 8) {
            const int kA = kk + t4;
            unsigned a[2][4];
#pragma unroll
            for (int mi = 0; mi < 2; mi++) {
                const int r0 = warp_m + mi * 16 + g;
                const int r1 = r0 + 8;
                a[mi][0] = __float_as_uint(as[asw(r0, kA)]);
                a[mi][1] = __float_as_uint(as[asw(r1, kA)]);
                a[mi][2] = __float_as_uint(as[asw(r0, kA + 4)]);
                a[mi][3] = __float_as_uint(as[asw(r1, kA + 4)]);
            }
#pragma unroll
            for (int nj = 0; nj < 8; nj++) {
                const int col = warp_n + nj * 8 + g;
                unsigned b0 = __float_as_uint(bs[bsw256(kA, col)]);
                unsigned b1 = __float_as_uint(bs[bsw256(kA + 4, col)]);
                mma_tf32(c[0][nj], a[0], b0, b1);
                mma_tf32(c[1][nj], a[1], b0, b1);
            }
        }
        __syncthreads();
    }

#pragma unroll
    for (int mi = 0; mi < 2; mi++) {
        const int r0 = bm + warp_m + mi * 16 + g;
#pragma unroll
        for (int nj = 0; nj < 8; nj++) {
            const int col = warp_n + nj * 8 + 2 * t4;
            const float bx = bias[col], by = bias[col + 1];
            float2 v0 = make_float2(c[mi][nj][0] + bx, c[mi][nj][1] + by);
            float2 v1 = make_float2(c[mi][nj][2] + bx, c[mi][nj][3] + by);
            *reinterpret_cast<float2*>(C + (size_t)r0 * 256 + col) = v0;
            *reinterpret_cast<float2*>(C + (size_t)(r0 + 8) * 256 + col) = v1;
        }
    }
}

// ============ guarded TF32 GEMM: C[M,N] = A[M,K]@B[K,N] + bias =============
// BM=128, BN=128, BK=32, 256 threads, warp tile 32x64.  K % 32 == 0.
// Row/col clamps in the loader (garbage compute, guarded stores).
__global__ __launch_bounds__(256, 2) void gemm_tf32_g(
    const float* __restrict__ A, const float* __restrict__ B,
    const float* __restrict__ bias, float* __restrict__ C,
    int M, int N, int K)
{
    extern __shared__ float sm[];
    float* As = sm;          // [2][4096]
    float* Bs = sm + 8192;   // [2][4096]

    const int tid = threadIdx.x;
    const int wid = tid >> 5, lane = tid & 31;
    const int g = lane >> 2, t4 = lane & 3;
    const int bm = blockIdx.y * 128;
    const int bn = blockIdx.x * 128;
    const int warp_m = (wid >> 1) * 32;
    const int warp_n = (wid & 1) * 64;

    const unsigned smA = (unsigned)__cvta_generic_to_shared(As);
    const unsigned smB = (unsigned)__cvta_generic_to_shared(Bs);

    float c[2][8][4];
#pragma unroll
    for (int mi = 0; mi < 2; mi++)
#pragma unroll
        for (int nj = 0; nj < 8; nj++)
#pragma unroll
            for (int r = 0; r < 4; r++) c[mi][nj][r] = 0.f;

    const int nT = K / 32;

    auto load_stage = [&](int t, int s) {
#pragma unroll
        for (int p = 0; p < 4; p++) {
            int ci = p * 256 + tid;
            int m = ci >> 3, k4 = (ci & 7) << 2;
            int gr = bm + m; if (gr > M - 1) gr = M - 1;
            cp16(smA + (unsigned)(s * 4096 + asw(m, k4)) * 4u,
                 A + (size_t)gr * K + t * 32 + k4);
        }
#pragma unroll
        for (int p = 0; p < 4; p++) {
            int ci = p * 256 + tid;
            int k = ci >> 5, n4 = (ci & 31) << 2;
            int gc = bn + n4; if (gc > N - 4) gc = N - 4;
            cp16(smB + (unsigned)(s * 4096 + bsw128(k, n4)) * 4u,
                 B + (size_t)(t * 32 + k) * N + gc);
        }
    };

    load_stage(0, 0);
    asm volatile("cp.async.commit_group;\n");

#pragma unroll 1
    for (int t = 0; t < nT; t++) {
        if (t + 1 < nT) {
            load_stage(t + 1, (t + 1) & 1);
            asm volatile("cp.async.commit_group;\n");
            asm volatile("cp.async.wait_group 1;\n");
        } else {
            asm volatile("cp.async.wait_group 0;\n");
        }
        __syncthreads();

        float* as = As + (t & 1) * 4096;
        float* bs = Bs + (t & 1) * 4096;

#pragma unroll
        for (int p = 0; p < 4; p++) cvt4(as + (p * 256 + tid) * 4);
#pragma unroll
        for (int p = 0; p < 4; p++) cvt4(bs + (p * 256 + tid) * 4);
        __syncthreads();

#pragma unroll
        for (int kk = 0; kk < 32; kk += 8) {
            const int kA = kk + t4;
            unsigned a[2][4];
#pragma unroll
            for (int mi = 0; mi < 2; mi++) {
                const int r0 = warp_m + mi * 16 + g;
                const int r1 = r0 + 8;
                a[mi][0] = __float_as_uint(as[asw(r0, kA)]);
                a[mi][1] = __float_as_uint(as[asw(r1, kA)]);
                a[mi][2] = __float_as_uint(as[asw(r0, kA + 4)]);
                a[mi][3] = __float_as_uint(as[asw(r1, kA + 4)]);
            }
#pragma unroll
            for (int nj = 0; nj < 8; nj++) {
                const int col = warp_n + nj * 8 + g;
                unsigned b0 = __float_as_uint(bs[bsw128(kA, col)]);
                unsigned b1 = __float_as_uint(bs[bsw128(kA + 4, col)]);
                mma_tf32(c[0][nj], a[0], b0, b1);
                mma_tf32(c[1][nj], a[1], b0, b1);
            }
        }
        __syncthreads();
    }

#pragma unroll
    for (int mi = 0; mi < 2; mi++) {
        const int r0 = bm + warp_m + mi * 16 + g;
#pragma unroll
        for (int nj = 0; nj < 8; nj++) {
            const int col = bn + warp_n + nj * 8 + 2 * t4;
            if (col + 1 < N) {
                const float bx = bias[col], by = bias[col + 1];
                if (r0 < M) {
                    float2 v0 = make_float2(c[mi][nj][0] + bx, c[mi][nj][1] + by);
                    *reinterpret_cast<float2*>(C + (size_t)r0 * N + col) = v0;
                }
                if (r0 + 8 < M) {
                    float2 v1 = make_float2(c[mi][nj][2] + bx, c[mi][nj][3] + by);
                    *reinterpret_cast<float2*>(C + (size_t)(r0 + 8) * N + col) = v1;
                }
            }
        }
    }
}

// ---------------- concat W_off|W_attn (runs every call; tiny) --------------
__global__ void concat_w(const float* __restrict__ W_off, const float* __restrict__ b_off,
                         const float* __restrict__ W_attn, const float* __restrict__ b_attn,
                         float* __restrict__ Wcat, float* __restrict__ bcat)
{
    int i = blockIdx.x * blockDim.x + threadIdx.x;
    if (i < DM * QS) {
        int r = i / QS, col = i % QS;
        Wcat[i] = (col < NOFF) ? W_off[r * NOFF + col] : W_attn[r * NATT + col - NOFF];
    }
    if (i < QS)
        bcat[i] = (i < NOFF) ? b_off[i] : b_attn[i - NOFF];
}

// ---------------- sampling: one warp per (b, q, h) ------------------------
__global__ __launch_bounds__(256) void msda_sample(
    const float* __restrict__ refp_g,   // [BS, NQ, NL, 2]
    const float* __restrict__ qproj_g,  // [BS, NQ, QS]  (off | att)
    const float* __restrict__ value_g,  // [BS, SUMHW, DM]
    float* __restrict__ acc_g)          // [BS, NQ, DM]
{
    const int gwarp = (blockIdx.x * blockDim.x + threadIdx.x) >> 5;
    const int lane  = threadIdx.x & 31;
    if (gwarp >= BS * NQ * NH) return;

    const int h  = gwarp & (NH - 1);
    const int bq = gwarp >> 3;
    const int b  = bq / NQ;

    const float* att = qproj_g + (size_t)bq * QS + NOFF + h * (NL * NP);
    float w[NL * NP];
    float mx = -INFINITY;
#pragma unroll
    for (int i = 0; i < NL * NP; i++) { w[i] = att[i]; mx = fmaxf(mx, w[i]); }
    float sum = 0.f;
#pragma unroll
    for (int i = 0; i < NL * NP; i++) { w[i] = expf(w[i] - mx); sum += w[i]; }
    const float inv = 1.f / sum;
#pragma unroll
    for (int i = 0; i < NL * NP; i++) w[i] *= inv;

    const float* off = qproj_g + (size_t)bq * QS + h * (NL * NP * 2);
    const float* rp  = refp_g + (size_t)bq * (NL * 2);

    const int d = h * DH + lane;
    const float* vb = value_g + (size_t)b * SUMHW * DM + d;

    const int Hs[NL] = {128, 64, 32};
    const int Ws[NL] = {128, 64, 32};
    const int St[NL] = {0, 16384, 20480};

    float a = 0.f;
#pragma unroll
    for (int l = 0; l < NL; l++) {
        const int Wl = Ws[l], Hl = Hs[l], st = St[l];
        const float rx = rp[l * 2 + 0] * (float)Wl;
        const float ry = rp[l * 2 + 1] * (float)Hl;
#pragma unroll
        for (int p = 0; p < NP; p++) {
            const float px = rx + off[l * (NP * 2) + p * 2 + 0] - 0.5f;
            const float py = ry + off[l * (NP * 2) + p * 2 + 1] - 0.5f;
            const float fx = floorf(px), fy = floorf(py);
            const float lx = px - fx, ly = py - fy;
            const int x0 = (int)fx, y0 = (int)fy;
            const float aw = w[l * NP + p];

            const float w00 = (1.f - lx) * (1.f - ly);
            const float w10 = lx * (1.f - ly);
            const float w01 = (1.f - lx) * ly;
            const float w11 = lx * ly;

            float s = 0.f;
            if (x0 >= 0 && x0 < Wl && y0 >= 0 && y0 < Hl)
                s = fmaf(w00, vb[(size_t)(st + y0 * Wl + x0) * DM], s);
            if (x0 + 1 >= 0 && x0 + 1 < Wl && y0 >= 0 && y0 < Hl)
                s = fmaf(w10, vb[(size_t)(st + y0 * Wl + x0 + 1) * DM], s);
            if (x0 >= 0 && x0 < Wl && y0 + 1 >= 0 && y0 + 1 < Hl)
                s = fmaf(w01, vb[(size_t)(st + (y0 + 1) * Wl + x0) * DM], s);
            if (x0 + 1 >= 0 && x0 + 1 < Wl && y0 + 1 >= 0 && y0 + 1 < Hl)
                s = fmaf(w11, vb[(size_t)(st + (y0 + 1) * Wl + x0 + 1) * DM], s);
            a = fmaf(aw, s, a);
        }
    }
    acc_g[(size_t)bq * DM + d] = a;
}

// ---------------- launch ---------------------------------------------------
extern "C" void kernel_launch(void* const* d_in, const int* in_sizes, int n_in,
                              void* d_out, int out_size)
{
    const float* query  = (const float*)d_in[0];
    const float* refpts = (const float*)d_in[1];
    const float* inflat = (const float*)d_in[2];
    const float* W_off  = (const float*)d_in[5];
    const float* b_off  = (const float*)d_in[6];
    const float* W_attn = (const float*)d_in[7];
    const float* b_attn = (const float*)d_in[8];
    const float* W_val  = (const float*)d_in[9];
    const float* b_val  = (const float*)d_in[10];
    const float* W_out  = (const float*)d_in[11];
    const float* b_out  = (const float*)d_in[12];
    float* out = (float*)d_out;

    float *value, *qproj, *acc, *wcat, *bcat;
    cudaGetSymbolAddress((void**)&value, g_value);
    cudaGetSymbolAddress((void**)&qproj, g_qproj);
    cudaGetSymbolAddress((void**)&acc,   g_acc);
    cudaGetSymbolAddress((void**)&wcat,  g_wcat);
    cudaGetSymbolAddress((void**)&bcat,  g_bcat);

    const int MQ = BS * NQ;          // 7200
    const int MV = BS * SUMHW;       // 172032

    const int smem_g = 2 * 2 * 4096 * (int)sizeof(float);                 // 64 KB
    const int smem_v = (2 * 4096 + 2 * 8192) * (int)sizeof(float);        // 96 KB
    cudaFuncSetAttribute(gemm_tf32_g,   cudaFuncAttributeMaxDynamicSharedMemorySize, smem_g);
    cudaFuncSetAttribute(gemm_tf32_val, cudaFuncAttributeMaxDynamicSharedMemorySize, smem_v);

    // 0) concat q-side weights
    concat_w<<<(DM * QS + 255) / 256, 256>>>(W_off, b_off, W_attn, b_attn, wcat, bcat);

    // 1) fused q projection: [7200,256] @ [256,288] -> qproj (off | att)
    gemm_tf32_g<<<dim3(3, (MQ + 127) / 128), 256, smem_g>>>(
        query, wcat, bcat, qproj, MQ, QS, DM);

    // 2) value projection: [172032,256] @ [256,256]
    gemm_tf32_val<<<MV / 128, 512, smem_v>>>(inflat, W_val, b_val, value);

    // 3) sampling
    {
        const int warps = BS * NQ * NH;
        const int blocks = (warps * 32 + 255) / 256;
        msda_sample<<<blocks, 256>>>(refpts, qproj, value, acc);
    }

    // 4) output projection: [7200,256] @ [256,256] -> d_out
    gemm_tf32_g<<<dim3(2, (MQ + 127) / 128), 256, smem_g>>>(
        acc, W_out, b_out, out, MQ, DM, DM);
}

// round 5
// speedup vs baseline: 2.6991x; 1.0117x over previous
#include <cuda_runtime.h>
#include <math.h>

// ---------------- problem constants ----------------
#define BS 8
#define NQ 900
#define DM 256
#define NH 8
#define NL 3
#define NP 4
#define DH 32
#define SUMHW 21504           // 128*128 + 64*64 + 32*32
#define NOFF 192              // NH*NL*NP*2
#define NATT 96               // NH*NL*NP
#define QS  (NOFF + NATT)     // 288

// ---------------- scratch ----------------
__device__ float g_value[(size_t)BS * SUMHW * DM];   // 176 MB
__device__ float g_qproj[(size_t)BS * NQ * QS];      // 8.3 MB
__device__ float g_acc[(size_t)BS * NQ * DM];
__device__ float g_wcat[DM * QS];
__device__ float g_bcat[QS];

// ---------------- ptx helpers ----------------
__device__ __forceinline__ void cp16(unsigned dst, const void* src) {
    asm volatile("cp.async.cg.shared.global [%0], [%1], 16;\n" :: "r"(dst), "l"(src));
}
__device__ __forceinline__ float tf32f(float x) {
    unsigned u;
    asm("cvt.rna.tf32.f32 %0, %1;\n" : "=r"(u) : "f"(x));
    return __uint_as_float(u);
}
__device__ __forceinline__ float4 tf32f4(float4 v) {
    v.x = tf32f(v.x); v.y = tf32f(v.y); v.z = tf32f(v.z); v.w = tf32f(v.w);
    return v;
}
__device__ __forceinline__ void mma_tf32(float c[4], const unsigned a[4],
                                         unsigned b0, unsigned b1) {
    asm volatile(
        "mma.sync.aligned.m16n8k8.row.col.f32.tf32.tf32.f32 "
        "{%0,%1,%2,%3}, {%4,%5,%6,%7}, {%8,%9}, {%0,%1,%2,%3};\n"
        : "+f"(c[0]), "+f"(c[1]), "+f"(c[2]), "+f"(c[3])
        : "r"(a[0]), "r"(a[1]), "r"(a[2]), "r"(a[3]), "r"(b0), "r"(b1));
}

// smem swizzles (float units) — conflict-free for both STS and frag LDS
__device__ __forceinline__ int asw(int m, int k)    { return m * 32  + (k ^ ((m & 7) << 2)); }
__device__ __forceinline__ int bsw128(int k, int n) { return k * 128 + (n ^ ((k & 3) << 3)); }

// in-place tf32 round of a float4 in smem (used by guarded GEMM)
__device__ __forceinline__ void cvt4(float* p) {
    *reinterpret_cast<float4*>(p) = tf32f4(*reinterpret_cast<float4*>(p));
}

// ============ value GEMM: C[M,256] = A[M,256] @ B[256,256] + bias ==========
// BM=128, BN=128, BK=32, 256 threads, warp tile 32x64.
// LDG.128 -> cvt.rna.tf32 (in regs) -> STS.128, double-buffered smem,
// one __syncthreads per k-tile, occupancy 2.
__global__ __launch_bounds__(256, 2) void gemm_tf32_val2(
    const float* __restrict__ A, const float* __restrict__ B,
    const float* __restrict__ bias, float* __restrict__ C)
{
    extern __shared__ float sm[];
    float* As = sm;           // [2][4096]
    float* Bs = sm + 8192;    // [2][4096]

    const int tid = threadIdx.x;
    const int wid = tid >> 5, lane = tid & 31;
    const int g = lane >> 2, t4 = lane & 3;
    const int bm = blockIdx.y * 128;
    const int bn = blockIdx.x * 128;
    const int warp_m = (wid >> 1) * 32;   // 0,32,64,96
    const int warp_n = (wid & 1) * 64;    // 0,64

    // loader coordinates
    const int aM  = tid >> 1;             // ci = tid*2 .. : A as 2 float4 of 8 k? no:
    // A tile: 128x32 floats = 4096 = 256 thr * 4 float4.  ci = p*256+tid
    // B tile: 32x128 floats = 4096 = 256 thr * 4 float4.

    float4 ra[4], rb[4];

    auto ldg_stage = [&](int t) {
        const float* Ag = A + (size_t)bm * 256 + t * 32;
#pragma unroll
        for (int p = 0; p < 4; p++) {
            int ci = p * 256 + tid;
            int m = ci >> 3, k4 = (ci & 7) << 2;
            ra[p] = *reinterpret_cast<const float4*>(Ag + (size_t)m * 256 + k4);
        }
        const float* Bg = B + (size_t)(t * 32) * 256 + bn;
#pragma unroll
        for (int p = 0; p < 4; p++) {
            int ci = p * 256 + tid;
            int k = ci >> 5, n4 = (ci & 31) << 2;
            rb[p] = *reinterpret_cast<const float4*>(Bg + (size_t)k * 256 + n4);
        }
    };
    auto sts_stage = [&](int s) {
        float* as = As + s * 4096;
        float* bs = Bs + s * 4096;
#pragma unroll
        for (int p = 0; p < 4; p++) {
            int ci = p * 256 + tid;
            int m = ci >> 3, k4 = (ci & 7) << 2;
            *reinterpret_cast<float4*>(as + asw(m, k4)) = tf32f4(ra[p]);
        }
#pragma unroll
        for (int p = 0; p < 4; p++) {
            int ci = p * 256 + tid;
            int k = ci >> 5, n4 = (ci & 31) << 2;
            *reinterpret_cast<float4*>(bs + bsw128(k, n4)) = tf32f4(rb[p]);
        }
    };

    float c[2][8][4];
#pragma unroll
    for (int mi = 0; mi < 2; mi++)
#pragma unroll
        for (int nj = 0; nj < 8; nj++)
#pragma unroll
            for (int r = 0; r < 4; r++) c[mi][nj][r] = 0.f;

    ldg_stage(0);
    sts_stage(0);

#pragma unroll 1
    for (int t = 0; t < 8; t++) {
        if (t + 1 < 8) ldg_stage(t + 1);       // LDG early: latency hides under MMAs
        __syncthreads();                        // stage t smem visible

        const float* as = As + (t & 1) * 4096;
        const float* bs = Bs + (t & 1) * 4096;

#pragma unroll
        for (int kk = 0; kk < 32; kk += 8) {
            const int kA = kk + t4;
            unsigned a[2][4];
#pragma unroll
            for (int mi = 0; mi < 2; mi++) {
                const int r0 = warp_m + mi * 16 + g;
                const int r1 = r0 + 8;
                a[mi][0] = __float_as_uint(as[asw(r0, kA)]);
                a[mi][1] = __float_as_uint(as[asw(r1, kA)]);
                a[mi][2] = __float_as_uint(as[asw(r0, kA + 4)]);
                a[mi][3] = __float_as_uint(as[asw(r1, kA + 4)]);
            }
#pragma unroll
            for (int nj = 0; nj < 8; nj++) {
                const int col = warp_n + nj * 8 + g;
                unsigned b0 = __float_as_uint(bs[bsw128(kA, col)]);
                unsigned b1 = __float_as_uint(bs[bsw128(kA + 4, col)]);
                mma_tf32(c[0][nj], a[0], b0, b1);
                mma_tf32(c[1][nj], a[1], b0, b1);
            }
        }

        if (t + 1 < 8) {
            __syncthreads();                    // everyone done reading stage t^... wait:
            sts_stage((t + 1) & 1);             // write OTHER buffer
        }
    }

#pragma unroll
    for (int mi = 0; mi < 2; mi++) {
        const int r0 = bm + warp_m + mi * 16 + g;
#pragma unroll
        for (int nj = 0; nj < 8; nj++) {
            const int col = bn + warp_n + nj * 8 + 2 * t4;
            const float bx = bias[col], by = bias[col + 1];
            float2 v0 = make_float2(c[mi][nj][0] + bx, c[mi][nj][1] + by);
            float2 v1 = make_float2(c[mi][nj][2] + bx, c[mi][nj][3] + by);
            *reinterpret_cast<float2*>(C + (size_t)r0 * 256 + col) = v0;
            *reinterpret_cast<float2*>(C + (size_t)(r0 + 8) * 256 + col) = v1;
        }
    }
}

// ============ guarded TF32 GEMM (q-side / out projections) ================
__global__ __launch_bounds__(256, 2) void gemm_tf32_g(
    const float* __restrict__ A, const float* __restrict__ B,
    const float* __restrict__ bias, float* __restrict__ C,
    int M, int N, int K)
{
    extern __shared__ float sm[];
    float* As = sm;          // [2][4096]
    float* Bs = sm + 8192;   // [2][4096]

    const int tid = threadIdx.x;
    const int wid = tid >> 5, lane = tid & 31;
    const int g = lane >> 2, t4 = lane & 3;
    const int bm = blockIdx.y * 128;
    const int bn = blockIdx.x * 128;
    const int warp_m = (wid >> 1) * 32;
    const int warp_n = (wid & 1) * 64;

    const unsigned smA = (unsigned)__cvta_generic_to_shared(As);
    const unsigned smB = (unsigned)__cvta_generic_to_shared(Bs);

    float c[2][8][4];
#pragma unroll
    for (int mi = 0; mi < 2; mi++)
#pragma unroll
        for (int nj = 0; nj < 8; nj++)
#pragma unroll
            for (int r = 0; r < 4; r++) c[mi][nj][r] = 0.f;

    const int nT = K / 32;

    auto load_stage = [&](int t, int s) {
#pragma unroll
        for (int p = 0; p < 4; p++) {
            int ci = p * 256 + tid;
            int m = ci >> 3, k4 = (ci & 7) << 2;
            int gr = bm + m; if (gr > M - 1) gr = M - 1;
            cp16(smA + (unsigned)(s * 4096 + asw(m, k4)) * 4u,
                 A + (size_t)gr * K + t * 32 + k4);
        }
#pragma unroll
        for (int p = 0; p < 4; p++) {
            int ci = p * 256 + tid;
            int k = ci >> 5, n4 = (ci & 31) << 2;
            int gc = bn + n4; if (gc > N - 4) gc = N - 4;
            cp16(smB + (unsigned)(s * 4096 + bsw128(k, n4)) * 4u,
                 B + (size_t)(t * 32 + k) * N + gc);
        }
    };

    load_stage(0, 0);
    asm volatile("cp.async.commit_group;\n");

#pragma unroll 1
    for (int t = 0; t < nT; t++) {
        if (t + 1 < nT) {
            load_stage(t + 1, (t + 1) & 1);
            asm volatile("cp.async.commit_group;\n");
            asm volatile("cp.async.wait_group 1;\n");
        } else {
            asm volatile("cp.async.wait_group 0;\n");
        }
        __syncthreads();

        float* as = As + (t & 1) * 4096;
        float* bs = Bs + (t & 1) * 4096;

#pragma unroll
        for (int p = 0; p < 4; p++) cvt4(as + (p * 256 + tid) * 4);
#pragma unroll
        for (int p = 0; p < 4; p++) cvt4(bs + (p * 256 + tid) * 4);
        __syncthreads();

#pragma unroll
        for (int kk = 0; kk < 32; kk += 8) {
            const int kA = kk + t4;
            unsigned a[2][4];
#pragma unroll
            for (int mi = 0; mi < 2; mi++) {
                const int r0 = warp_m + mi * 16 + g;
                const int r1 = r0 + 8;
                a[mi][0] = __float_as_uint(as[asw(r0, kA)]);
                a[mi][1] = __float_as_uint(as[asw(r1, kA)]);
                a[mi][2] = __float_as_uint(as[asw(r0, kA + 4)]);
                a[mi][3] = __float_as_uint(as[asw(r1, kA + 4)]);
            }
#pragma unroll
            for (int nj = 0; nj < 8; nj++) {
                const int col = warp_n + nj * 8 + g;
                unsigned b0 = __float_as_uint(bs[bsw128(kA, col)]);
                unsigned b1 = __float_as_uint(bs[bsw128(kA + 4, col)]);
                mma_tf32(c[0][nj], a[0], b0, b1);
                mma_tf32(c[1][nj], a[1], b0, b1);
            }
        }
        __syncthreads();
    }

#pragma unroll
    for (int mi = 0; mi < 2; mi++) {
        const int r0 = bm + warp_m + mi * 16 + g;
#pragma unroll
        for (int nj = 0; nj < 8; nj++) {
            const int col = bn + warp_n + nj * 8 + 2 * t4;
            if (col + 1 < N) {
                const float bx = bias[col], by = bias[col + 1];
                if (r0 < M) {
                    float2 v0 = make_float2(c[mi][nj][0] + bx, c[mi][nj][1] + by);
                    *reinterpret_cast<float2*>(C + (size_t)r0 * N + col) = v0;
                }
                if (r0 + 8 < M) {
                    float2 v1 = make_float2(c[mi][nj][2] + bx, c[mi][nj][3] + by);
                    *reinterpret_cast<float2*>(C + (size_t)(r0 + 8) * N + col) = v1;
                }
            }
        }
    }
}

// ---------------- concat W_off|W_attn --------------------------------------
__global__ void concat_w(const float* __restrict__ W_off, const float* __restrict__ b_off,
                         const float* __restrict__ W_attn, const float* __restrict__ b_attn,
                         float* __restrict__ Wcat, float* __restrict__ bcat)
{
    int i = blockIdx.x * blockDim.x + threadIdx.x;
    if (i < DM * QS) {
        int r = i / QS, col = i % QS;
        Wcat[i] = (col < NOFF) ? W_off[r * NOFF + col] : W_attn[r * NATT + col - NOFF];
    }
    if (i < QS)
        bcat[i] = (i < NOFF) ? b_off[i] : b_attn[i - NOFF];
}

// ---------------- sampling: one warp per (b, q, h) ------------------------
__global__ __launch_bounds__(256) void msda_sample(
    const float* __restrict__ refp_g,   // [BS, NQ, NL, 2]
    const float* __restrict__ qproj_g,  // [BS, NQ, QS]  (off | att)
    const float* __restrict__ value_g,  // [BS, SUMHW, DM]
    float* __restrict__ acc_g)          // [BS, NQ, DM]
{
    const int gwarp = (blockIdx.x * blockDim.x + threadIdx.x) >> 5;
    const int lane  = threadIdx.x & 31;
    if (gwarp >= BS * NQ * NH) return;

    const int h  = gwarp & (NH - 1);
    const int bq = gwarp >> 3;
    const int b  = bq / NQ;

    const float* att = qproj_g + (size_t)bq * QS + NOFF + h * (NL * NP);
    float w[NL * NP];
    float mx = -INFINITY;
#pragma unroll
    for (int i = 0; i < NL * NP; i++) { w[i] = att[i]; mx = fmaxf(mx, w[i]); }
    float sum = 0.f;
#pragma unroll
    for (int i = 0; i < NL * NP; i++) { w[i] = expf(w[i] - mx); sum += w[i]; }
    const float inv = 1.f / sum;
#pragma unroll
    for (int i = 0; i < NL * NP; i++) w[i] *= inv;

    const float* off = qproj_g + (size_t)bq * QS + h * (NL * NP * 2);
    const float* rp  = refp_g + (size_t)bq * (NL * 2);

    const int d = h * DH + lane;
    const float* vb = value_g + (size_t)b * SUMHW * DM + d;

    const int Dims[NL] = {128, 64, 32};
    const int St[NL]   = {0, 16384, 20480};

    float a0 = 0.f, a1 = 0.f;
#pragma unroll
    for (int l = 0; l < NL; l++) {
        const int Wl = Dims[l], Hl = Dims[l], st = St[l];
        const float rx = rp[l * 2 + 0] * (float)Wl;
        const float ry = rp[l * 2 + 1] * (float)Hl;
#pragma unroll
        for (int p = 0; p < NP; p++) {
            const float px = rx + off[l * (NP * 2) + p * 2 + 0] - 0.5f;
            const float py = ry + off[l * (NP * 2) + p * 2 + 1] - 0.5f;
            const float fx = floorf(px), fy = floorf(py);
            const float lx = px - fx, ly = py - fy;
            const int x0 = (int)fx, y0 = (int)fy;
            const float aw = w[l * NP + p];

            // validity masks folded into bilinear weights
            const bool vx0 = ((unsigned)x0       < (unsigned)Wl);
            const bool vx1 = ((unsigned)(x0 + 1) < (unsigned)Wl);
            const bool vy0 = ((unsigned)y0       < (unsigned)Hl);
            const bool vy1 = ((unsigned)(y0 + 1) < (unsigned)Hl);

            const float m00 = (vx0 && vy0) ? aw * (1.f - lx) * (1.f - ly) : 0.f;
            const float m10 = (vx1 && vy0) ? aw * lx * (1.f - ly) : 0.f;
            const float m01 = (vx0 && vy1) ? aw * (1.f - lx) * ly : 0.f;
            const float m11 = (vx1 && vy1) ? aw * lx * ly : 0.f;

            // clamped addresses (always-valid loads)
            const int cx0 = min(max(x0, 0), Wl - 1);
            const int cx1 = min(max(x0 + 1, 0), Wl - 1);
            const int cy0 = min(max(y0, 0), Hl - 1);
            const int cy1 = min(max(y0 + 1, 0), Hl - 1);

            const float* r0 = vb + (size_t)(st + cy0 * Wl) * DM;
            const float* r1 = vb + (size_t)(st + cy1 * Wl) * DM;

            const float v00 = r0[(size_t)cx0 * DM];
            const float v10 = r0[(size_t)cx1 * DM];
            const float v01 = r1[(size_t)cx0 * DM];
            const float v11 = r1[(size_t)cx1 * DM];

            a0 = fmaf(m00, v00, a0);
            a1 = fmaf(m10, v10, a1);
            a0 = fmaf(m01, v01, a0);
            a1 = fmaf(m11, v11, a1);
        }
    }
    acc_g[(size_t)bq * DM + d] = a0 + a1;
}

// ---------------- launch ---------------------------------------------------
extern "C" void kernel_launch(void* const* d_in, const int* in_sizes, int n_in,
                              void* d_out, int out_size)
{
    const float* query  = (const float*)d_in[0];
    const float* refpts = (const float*)d_in[1];
    const float* inflat = (const float*)d_in[2];
    const float* W_off  = (const float*)d_in[5];
    const float* b_off  = (const float*)d_in[6];
    const float* W_attn = (const float*)d_in[7];
    const float* b_attn = (const float*)d_in[8];
    const float* W_val  = (const float*)d_in[9];
    const float* b_val  = (const float*)d_in[10];
    const float* W_out  = (const float*)d_in[11];
    const float* b_out  = (const float*)d_in[12];
    float* out = (float*)d_out;

    float *value, *qproj, *acc, *wcat, *bcat;
    cudaGetSymbolAddress((void**)&value, g_value);
    cudaGetSymbolAddress((void**)&qproj, g_qproj);
    cudaGetSymbolAddress((void**)&acc,   g_acc);
    cudaGetSymbolAddress((void**)&wcat,  g_wcat);
    cudaGetSymbolAddress((void**)&bcat,  g_bcat);

    const int MQ = BS * NQ;          // 7200
    const int MV = BS * SUMHW;       // 172032

    const int smem_g = 2 * 2 * 4096 * (int)sizeof(float);   // 64 KB
    cudaFuncSetAttribute(gemm_tf32_g,    cudaFuncAttributeMaxDynamicSharedMemorySize, smem_g);
    cudaFuncSetAttribute(gemm_tf32_val2, cudaFuncAttributeMaxDynamicSharedMemorySize, smem_g);

    // 0) concat q-side weights
    concat_w<<<(DM * QS + 255) / 256, 256>>>(W_off, b_off, W_attn, b_attn, wcat, bcat);

    // 1) fused q projection: [7200,256] @ [256,288] -> qproj (off | att)
    gemm_tf32_g<<<dim3(3, (MQ + 127) / 128), 256, smem_g>>>(
        query, wcat, bcat, qproj, MQ, QS, DM);

    // 2) value projection: [172032,256] @ [256,256]
    gemm_tf32_val2<<<dim3(2, MV / 128), 256, smem_g>>>(inflat, W_val, b_val, value);

    // 3) sampling
    {
        const int warps = BS * NQ * NH;
        const int blocks = (warps * 32 + 255) / 256;
        msda_sample<<<blocks, 256>>>(refpts, qproj, value, acc);
    }

    // 4) output projection: [7200,256] @ [256,256] -> d_out
    gemm_tf32_g<<<dim3(2, (MQ + 127) / 128), 256, smem_g>>>(
        acc, W_out, b_out, out, MQ, DM, DM);
}

// round 8
// speedup vs baseline: 2.9750x; 1.1022x over previous
#include <cuda_runtime.h>
#include <cuda_fp16.h>
#include <math.h>

// ---------------- problem constants ----------------
#define BS 8
#define NQ 900
#define DM 256
#define NH 8
#define NL 3
#define NP 4
#define DH 32
#define SUMHW 21504           // 128*128 + 64*64 + 32*32
#define NOFF 192              // NH*NL*NP*2
#define NATT 96               // NH*NL*NP
#define QS  (NOFF + NATT)     // 288

// ---------------- scratch ----------------
__device__ float  g_value[(size_t)BS * SUMHW * DM];   // 176 MB
__device__ float  g_qproj[(size_t)BS * NQ * QS];      // 8.3 MB
__device__ float  g_acc[(size_t)BS * NQ * DM];
__device__ float  g_wcat[DM * QS];
__device__ float  g_bcat[QS];
__device__ __half g_wvalT_h[DM * DM];                 // W_val^T in fp16, [n][k]

// ---------------- ptx helpers ----------------
__device__ __forceinline__ void cp16(unsigned dst, const void* src) {
    asm volatile("cp.async.cg.shared.global [%0], [%1], 16;\n" :: "r"(dst), "l"(src));
}
__device__ __forceinline__ float tf32f(float x) {
    unsigned u;
    asm("cvt.rna.tf32.f32 %0, %1;\n" : "=r"(u) : "f"(x));
    return __uint_as_float(u);
}
__device__ __forceinline__ float4 tf32f4(float4 v) {
    v.x = tf32f(v.x); v.y = tf32f(v.y); v.z = tf32f(v.z); v.w = tf32f(v.w);
    return v;
}
__device__ __forceinline__ void mma_tf32(float c[4], const unsigned a[4],
                                         unsigned b0, unsigned b1) {
    asm volatile(
        "mma.sync.aligned.m16n8k8.row.col.f32.tf32.tf32.f32 "
        "{%0,%1,%2,%3}, {%4,%5,%6,%7}, {%8,%9}, {%0,%1,%2,%3};\n"
        : "+f"(c[0]), "+f"(c[1]), "+f"(c[2]), "+f"(c[3])
        : "r"(a[0]), "r"(a[1]), "r"(a[2]), "r"(a[3]), "r"(b0), "r"(b1));
}
__device__ __forceinline__ void mma_f16(float c[4], const unsigned a[4],
                                        unsigned b0, unsigned b1) {
    asm volatile(
        "mma.sync.aligned.m16n8k16.row.col.f32.f16.f16.f32 "
        "{%0,%1,%2,%3}, {%4,%5,%6,%7}, {%8,%9}, {%0,%1,%2,%3};\n"
        : "+f"(c[0]), "+f"(c[1]), "+f"(c[2]), "+f"(c[3])
        : "r"(a[0]), "r"(a[1]), "r"(a[2]), "r"(a[3]), "r"(b0), "r"(b1));
}

// smem swizzles (float units) for the tf32 GEMM
__device__ __forceinline__ int asw(int m, int k)    { return m * 32  + (k ^ ((m & 7) << 2)); }
__device__ __forceinline__ int bsw128(int k, int n) { return k * 128 + (n ^ ((k & 3) << 3)); }
__device__ __forceinline__ void cvt4(float* p) {
    *reinterpret_cast<float4*>(p) = tf32f4(*reinterpret_cast<float4*>(p));
}

// pack 8 floats -> 8 fp16 in a uint4
__device__ __forceinline__ uint4 pack8h(const float* f) {
    uint4 r;
    __half2 h;
    h = __floats2half2_rn(f[0], f[1]); r.x = *reinterpret_cast<unsigned*>(&h);
    h = __floats2half2_rn(f[2], f[3]); r.y = *reinterpret_cast<unsigned*>(&h);
    h = __floats2half2_rn(f[4], f[5]); r.z = *reinterpret_cast<unsigned*>(&h);
    h = __floats2half2_rn(f[6], f[7]); r.w = *reinterpret_cast<unsigned*>(&h);
    return r;
}

// ============ fp16 value GEMM: C[M,256] = A[M,256] @ Bt^T + bias ===========
// Bt = W_val^T fp16, [n=256][k=256].  BM=128, BN=128, BK=32, 256 threads,
// 8 warps, warp tile 32x64, m16n8k16.  Smem: half tiles, row stride 72
// halves (144B: 16B-aligned STS.128, conflict-free LDS.32 fragments).
#define VSTRIDE 72
#define VTILE   (128 * VSTRIDE)            // halves per tile buffer (9216)

__global__ __launch_bounds__(256, 2) void gemm_f16_val(
    const float* __restrict__ A, const __half* __restrict__ Bt,
    const float* __restrict__ bias, float* __restrict__ C)
{
    extern __shared__ __half smh[];
    __half* As = smh;                      // [2][VTILE]
    __half* Bs = smh + 2 * VTILE;          // [2][VTILE]

    const int tid = threadIdx.x;
    const int wid = tid >> 5, lane = tid & 31;
    const int g = lane >> 2, t4 = lane & 3;
    const int bm = blockIdx.y * 128;
    const int bn = blockIdx.x * 128;
    const int warp_m = (wid >> 1) * 32;    // 0,32,64,96
    const int warp_n = (wid & 1) * 64;     // 0,64

    // loader coords: 2 threads per row, 16 k-elements each
    const int lm = tid >> 1;               // 0..127 (row for A, col for B)
    const int lk = (tid & 1) * 16;         // 0 or 16

    float4 ra[4];
    uint4  rbv[2];

    auto ldg_stage = [&](int t) {
        const float* Ag = A + (size_t)(bm + lm) * 256 + t * 32 + lk;
#pragma unroll
        for (int p = 0; p < 4; p++)
            ra[p] = *reinterpret_cast<const float4*>(Ag + p * 4);
        const __half* Bg = Bt + (size_t)(bn + lm) * 256 + t * 32 + lk;
        rbv[0] = *reinterpret_cast<const uint4*>(Bg);
        rbv[1] = *reinterpret_cast<const uint4*>(Bg + 8);
    };
    auto sts_stage = [&](int s) {
        __half* as = As + s * VTILE + lm * VSTRIDE + lk;
        *reinterpret_cast<uint4*>(as)     = pack8h(&ra[0].x);
        *reinterpret_cast<uint4*>(as + 8) = pack8h(&ra[2].x);
        __half* bs = Bs + s * VTILE + lm * VSTRIDE + lk;
        *reinterpret_cast<uint4*>(bs)     = rbv[0];
        *reinterpret_cast<uint4*>(bs + 8) = rbv[1];
    };

    float c[2][8][4];
#pragma unroll
    for (int mi = 0; mi < 2; mi++)
#pragma unroll
        for (int nj = 0; nj < 8; nj++)
#pragma unroll
            for (int r = 0; r < 4; r++) c[mi][nj][r] = 0.f;

    ldg_stage(0);
    sts_stage(0);

#pragma unroll 1
    for (int t = 0; t < 8; t++) {
        if (t + 1 < 8) ldg_stage(t + 1);   // LDG early: latency hides under MMAs
        __syncthreads();                    // stage t smem visible

        const __half* as = As + (t & 1) * VTILE;
        const __half* bs = Bs + (t & 1) * VTILE;

#pragma unroll
        for (int kk = 0; kk < 32; kk += 16) {
            const int kA = kk + 2 * t4;
            unsigned a[2][4];
#pragma unroll
            for (int mi = 0; mi < 2; mi++) {
                const __half* ap = as + (warp_m + mi * 16 + g) * VSTRIDE + kA;
                a[mi][0] = *reinterpret_cast<const unsigned*>(ap);
                a[mi][1] = *reinterpret_cast<const unsigned*>(ap + 8 * VSTRIDE);
                a[mi][2] = *reinterpret_cast<const unsigned*>(ap + 8);
                a[mi][3] = *reinterpret_cast<const unsigned*>(ap + 8 * VSTRIDE + 8);
            }
#pragma unroll
            for (int nj = 0; nj < 8; nj++) {
                const __half* bp = bs + (warp_n + nj * 8 + g) * VSTRIDE + kA;
                unsigned b0 = *reinterpret_cast<const unsigned*>(bp);
                unsigned b1 = *reinterpret_cast<const unsigned*>(bp + 8);
                mma_f16(c[0][nj], a[0], b0, b1);
                mma_f16(c[1][nj], a[1], b0, b1);
            }
        }

        if (t + 1 < 8) {
            __syncthreads();
            sts_stage((t + 1) & 1);
        }
    }

    // ---- epilogue: bias + float2 stores ----
#pragma unroll
    for (int mi = 0; mi < 2; mi++) {
        const int r0 = bm + warp_m + mi * 16 + g;
#pragma unroll
        for (int nj = 0; nj < 8; nj++) {
            const int col = bn + warp_n + nj * 8 + 2 * t4;
            const float bx = bias[col], by = bias[col + 1];
            float2 v0 = make_float2(c[mi][nj][0] + bx, c[mi][nj][1] + by);
            float2 v1 = make_float2(c[mi][nj][2] + bx, c[mi][nj][3] + by);
            *reinterpret_cast<float2*>(C + (size_t)r0 * 256 + col) = v0;
            *reinterpret_cast<float2*>(C + (size_t)(r0 + 8) * 256 + col) = v1;
        }
    }
}

// ---------------- W_val transpose + fp16 convert (tiny prep) ---------------
__global__ void transpose_half(const float* __restrict__ W, __half* __restrict__ Wt)
{
    int i = blockIdx.x * blockDim.x + threadIdx.x;   // i = n*256 + k
    if (i < DM * DM) {
        int n = i >> 8, k = i & 255;
        Wt[i] = __float2half(W[k * DM + n]);
    }
}

// ============ guarded TF32 GEMM (q-side / out projections) ================
__global__ __launch_bounds__(256, 2) void gemm_tf32_g(
    const float* __restrict__ A, const float* __restrict__ B,
    const float* __restrict__ bias, float* __restrict__ C,
    int M, int N, int K)
{
    extern __shared__ float sm[];
    float* As = sm;          // [2][4096]
    float* Bs = sm + 8192;   // [2][4096]

    const int tid = threadIdx.x;
    const int wid = tid >> 5, lane = tid & 31;
    const int g = lane >> 2, t4 = lane & 3;
    const int bm = blockIdx.y * 128;
    const int bn = blockIdx.x * 128;
    const int warp_m = (wid >> 1) * 32;
    const int warp_n = (wid & 1) * 64;

    const unsigned smA = (unsigned)__cvta_generic_to_shared(As);
    const unsigned smB = (unsigned)__cvta_generic_to_shared(Bs);

    float c[2][8][4];
#pragma unroll
    for (int mi = 0; mi < 2; mi++)
#pragma unroll
        for (int nj = 0; nj < 8; nj++)
#pragma unroll
            for (int r = 0; r < 4; r++) c[mi][nj][r] = 0.f;

    const int nT = K / 32;

    auto load_stage = [&](int t, int s) {
#pragma unroll
        for (int p = 0; p < 4; p++) {
            int ci = p * 256 + tid;
            int m = ci >> 3, k4 = (ci & 7) << 2;
            int gr = bm + m; if (gr > M - 1) gr = M - 1;
            cp16(smA + (unsigned)(s * 4096 + asw(m, k4)) * 4u,
                 A + (size_t)gr * K + t * 32 + k4);
        }
#pragma unroll
        for (int p = 0; p < 4; p++) {
            int ci = p * 256 + tid;
            int k = ci >> 5, n4 = (ci & 31) << 2;
            int gc = bn + n4; if (gc > N - 4) gc = N - 4;
            cp16(smB + (unsigned)(s * 4096 + bsw128(k, n4)) * 4u,
                 B + (size_t)(t * 32 + k) * N + gc);
        }
    };

    load_stage(0, 0);
    asm volatile("cp.async.commit_group;\n");

#pragma unroll 1
    for (int t = 0; t < nT; t++) {
        if (t + 1 < nT) {
            load_stage(t + 1, (t + 1) & 1);
            asm volatile("cp.async.commit_group;\n");
            asm volatile("cp.async.wait_group 1;\n");
        } else {
            asm volatile("cp.async.wait_group 0;\n");
        }
        __syncthreads();

        float* as = As + (t & 1) * 4096;
        float* bs = Bs + (t & 1) * 4096;

#pragma unroll
        for (int p = 0; p < 4; p++) cvt4(as + (p * 256 + tid) * 4);
#pragma unroll
        for (int p = 0; p < 4; p++) cvt4(bs + (p * 256 + tid) * 4);
        __syncthreads();

#pragma unroll
        for (int kk = 0; kk < 32; kk += 8) {
            const int kA = kk + t4;
            unsigned a[2][4];
#pragma unroll
            for (int mi = 0; mi < 2; mi++) {
                const int r0 = warp_m + mi * 16 + g;
                const int r1 = r0 + 8;
                a[mi][0] = __float_as_uint(as[asw(r0, kA)]);
                a[mi][1] = __float_as_uint(as[asw(r1, kA)]);
                a[mi][2] = __float_as_uint(as[asw(r0, kA + 4)]);
                a[mi][3] = __float_as_uint(as[asw(r1, kA + 4)]);
            }
#pragma unroll
            for (int nj = 0; nj < 8; nj++) {
                const int col = warp_n + nj * 8 + g;
                unsigned b0 = __float_as_uint(bs[bsw128(kA, col)]);
                unsigned b1 = __float_as_uint(bs[bsw128(kA + 4, col)]);
                mma_tf32(c[0][nj], a[0], b0, b1);
                mma_tf32(c[1][nj], a[1], b0, b1);
            }
        }
        __syncthreads();
    }

#pragma unroll
    for (int mi = 0; mi < 2; mi++) {
        const int r0 = bm + warp_m + mi * 16 + g;
#pragma unroll
        for (int nj = 0; nj < 8; nj++) {
            const int col = bn + warp_n + nj * 8 + 2 * t4;
            if (col + 1 < N) {
                const float bx = bias[col], by = bias[col + 1];
                if (r0 < M) {
                    float2 v0 = make_float2(c[mi][nj][0] + bx, c[mi][nj][1] + by);
                    *reinterpret_cast<float2*>(C + (size_t)r0 * N + col) = v0;
                }
                if (r0 + 8 < M) {
                    float2 v1 = make_float2(c[mi][nj][2] + bx, c[mi][nj][3] + by);
                    *reinterpret_cast<float2*>(C + (size_t)(r0 + 8) * N + col) = v1;
                }
            }
        }
    }
}

// ---------------- concat W_off|W_attn --------------------------------------
__global__ void concat_w(const float* __restrict__ W_off, const float* __restrict__ b_off,
                         const float* __restrict__ W_attn, const float* __restrict__ b_attn,
                         float* __restrict__ Wcat, float* __restrict__ bcat)
{
    int i = blockIdx.x * blockDim.x + threadIdx.x;
    if (i < DM * QS) {
        int r = i / QS, col = i % QS;
        Wcat[i] = (col < NOFF) ? W_off[r * NOFF + col] : W_attn[r * NATT + col - NOFF];
    }
    if (i < QS)
        bcat[i] = (i < NOFF) ? b_off[i] : b_attn[i - NOFF];
}

// ---------------- sampling: one warp per (b, q, h) ------------------------
__global__ __launch_bounds__(256) void msda_sample(
    const float* __restrict__ refp_g,   // [BS, NQ, NL, 2]
    const float* __restrict__ qproj_g,  // [BS, NQ, QS]  (off | att)
    const float* __restrict__ value_g,  // [BS, SUMHW, DM]
    float* __restrict__ acc_g)          // [BS, NQ, DM]
{
    const int gwarp = (blockIdx.x * blockDim.x + threadIdx.x) >> 5;
    const int lane  = threadIdx.x & 31;
    if (gwarp >= BS * NQ * NH) return;

    const int h  = gwarp & (NH - 1);
    const int bq = gwarp >> 3;
    const int b  = bq / NQ;

    const float* att = qproj_g + (size_t)bq * QS + NOFF + h * (NL * NP);
    float w[NL * NP];
    float mx = -INFINITY;
#pragma unroll
    for (int i = 0; i < NL * NP; i++) { w[i] = att[i]; mx = fmaxf(mx, w[i]); }
    float sum = 0.f;
#pragma unroll
    for (int i = 0; i < NL * NP; i++) { w[i] = expf(w[i] - mx); sum += w[i]; }
    const float inv = 1.f / sum;
#pragma unroll
    for (int i = 0; i < NL * NP; i++) w[i] *= inv;

    const float* off = qproj_g + (size_t)bq * QS + h * (NL * NP * 2);
    const float* rp  = refp_g + (size_t)bq * (NL * 2);

    const int d = h * DH + lane;
    const float* vb = value_g + (size_t)b * SUMHW * DM + d;

    const int Hs[NL] = {128, 64, 32};
    const int Ws[NL] = {128, 64, 32};
    const int St[NL] = {0, 16384, 20480};

    float a = 0.f;
#pragma unroll
    for (int l = 0; l < NL; l++) {
        const int Wl = Ws[l], Hl = Hs[l], st = St[l];
        const float rx = rp[l * 2 + 0] * (float)Wl;
        const float ry = rp[l * 2 + 1] * (float)Hl;
#pragma unroll
        for (int p = 0; p < NP; p++) {
            const float px = rx + off[l * (NP * 2) + p * 2 + 0] - 0.5f;
            const float py = ry + off[l * (NP * 2) + p * 2 + 1] - 0.5f;
            const float fx = floorf(px), fy = floorf(py);
            const float lx = px - fx, ly = py - fy;
            const int x0 = (int)fx, y0 = (int)fy;
            const float aw = w[l * NP + p];

            const float w00 = (1.f - lx) * (1.f - ly);
            const float w10 = lx * (1.f - ly);
            const float w01 = (1.f - lx) * ly;
            const float w11 = lx * ly;

            float s = 0.f;
            if (x0 >= 0 && x0 < Wl && y0 >= 0 && y0 < Hl)
                s = fmaf(w00, vb[(size_t)(st + y0 * Wl + x0) * DM], s);
            if (x0 + 1 >= 0 && x0 + 1 < Wl && y0 >= 0 && y0 < Hl)
                s = fmaf(w10, vb[(size_t)(st + y0 * Wl + x0 + 1) * DM], s);
            if (x0 >= 0 && x0 < Wl && y0 + 1 >= 0 && y0 + 1 < Hl)
                s = fmaf(w01, vb[(size_t)(st + (y0 + 1) * Wl + x0) * DM], s);
            if (x0 + 1 >= 0 && x0 + 1 < Wl && y0 + 1 >= 0 && y0 + 1 < Hl)
                s = fmaf(w11, vb[(size_t)(st + (y0 + 1) * Wl + x0 + 1) * DM], s);
            a = fmaf(aw, s, a);
        }
    }
    acc_g[(size_t)bq * DM + d] = a;
}

// ---------------- launch ---------------------------------------------------
extern "C" void kernel_launch(void* const* d_in, const int* in_sizes, int n_in,
                              void* d_out, int out_size)
{
    const float* query  = (const float*)d_in[0];
    const float* refpts = (const float*)d_in[1];
    const float* inflat = (const float*)d_in[2];
    const float* W_off  = (const float*)d_in[5];
    const float* b_off  = (const float*)d_in[6];
    const float* W_attn = (const float*)d_in[7];
    const float* b_attn = (const float*)d_in[8];
    const float* W_val  = (const float*)d_in[9];
    const float* b_val  = (const float*)d_in[10];
    const float* W_out  = (const float*)d_in[11];
    const float* b_out  = (const float*)d_in[12];
    float* out = (float*)d_out;

    float *value, *qproj, *acc, *wcat, *bcat;
    __half* wvalT;
    cudaGetSymbolAddress((void**)&value, g_value);
    cudaGetSymbolAddress((void**)&qproj, g_qproj);
    cudaGetSymbolAddress((void**)&acc,   g_acc);
    cudaGetSymbolAddress((void**)&wcat,  g_wcat);
    cudaGetSymbolAddress((void**)&bcat,  g_bcat);
    cudaGetSymbolAddress((void**)&wvalT, g_wvalT_h);

    const int MQ = BS * NQ;          // 7200
    const int MV = BS * SUMHW;       // 172032

    const int smem_g = 2 * 2 * 4096 * (int)sizeof(float);        // 64 KB
    const int smem_v = 4 * VTILE * (int)sizeof(__half);          // 73728 B
    cudaFuncSetAttribute(gemm_tf32_g,  cudaFuncAttributeMaxDynamicSharedMemorySize, smem_g);
    cudaFuncSetAttribute(gemm_f16_val, cudaFuncAttributeMaxDynamicSharedMemorySize, smem_v);

    // 0) weight prep (tiny)
    concat_w<<<(DM * QS + 255) / 256, 256>>>(W_off, b_off, W_attn, b_attn, wcat, bcat);
    transpose_half<<<(DM * DM + 255) / 256, 256>>>(W_val, wvalT);

    // 1) fused q projection: [7200,256] @ [256,288] -> qproj (off | att)
    gemm_tf32_g<<<dim3(3, (MQ + 127) / 128), 256, smem_g>>>(
        query, wcat, bcat, qproj, MQ, QS, DM);

    // 2) value projection (fp16 tensor cores): [172032,256] @ [256,256]
    gemm_f16_val<<<dim3(2, MV / 128), 256, smem_v>>>(inflat, wvalT, b_val, value);

    // 3) sampling
    {
        const int warps = BS * NQ * NH;
        const int blocks = (warps * 32 + 255) / 256;
        msda_sample<<<blocks, 256>>>(refpts, qproj, value, acc);
    }

    // 4) output projection: [7200,256] @ [256,256] -> d_out
    gemm_tf32_g<<<dim3(2, (MQ + 127) / 128), 256, smem_g>>>(
        acc, W_out, b_out, out, MQ, DM, DM);
}

// round 10
// speedup vs baseline: 3.4437x; 1.1575x over previous
#include <cuda_runtime.h>
#include <cuda_fp16.h>
#include <math.h>

// ---------------- problem constants ----------------
#define BS 8
#define NQ 900
#define DM 256
#define NH 8
#define NL 3
#define NP 4
#define DH 32
#define SUMHW 21504           // 128*128 + 64*64 + 32*32
#define NOFF 192              // NH*NL*NP*2
#define NATT 96               // NH*NL*NP
#define QS  (NOFF + NATT)     // 288

// ---------------- scratch ----------------
__device__ float  g_value[(size_t)BS * SUMHW * DM];   // 176 MB
__device__ float  g_qproj[(size_t)BS * NQ * QS];      // 8.3 MB
__device__ float  g_acc[(size_t)BS * NQ * DM];
__device__ float  g_wcat[DM * QS];
__device__ float  g_bcat[QS];
__device__ __half g_wvalT_h[DM * DM];                 // W_val^T in fp16, [n][k]

// ---------------- ptx helpers ----------------
__device__ __forceinline__ void cp16(unsigned dst, const void* src) {
    asm volatile("cp.async.cg.shared.global [%0], [%1], 16;\n" :: "r"(dst), "l"(src));
}
__device__ __forceinline__ float tf32f(float x) {
    unsigned u;
    asm("cvt.rna.tf32.f32 %0, %1;\n" : "=r"(u) : "f"(x));
    return __uint_as_float(u);
}
__device__ __forceinline__ float4 tf32f4(float4 v) {
    v.x = tf32f(v.x); v.y = tf32f(v.y); v.z = tf32f(v.z); v.w = tf32f(v.w);
    return v;
}
__device__ __forceinline__ void mma_tf32(float c[4], const unsigned a[4],
                                         unsigned b0, unsigned b1) {
    asm volatile(
        "mma.sync.aligned.m16n8k8.row.col.f32.tf32.tf32.f32 "
        "{%0,%1,%2,%3}, {%4,%5,%6,%7}, {%8,%9}, {%0,%1,%2,%3};\n"
        : "+f"(c[0]), "+f"(c[1]), "+f"(c[2]), "+f"(c[3])
        : "r"(a[0]), "r"(a[1]), "r"(a[2]), "r"(a[3]), "r"(b0), "r"(b1));
}
__device__ __forceinline__ void mma_f16(float c[4], const unsigned a[4],
                                        unsigned b0, unsigned b1) {
    asm volatile(
        "mma.sync.aligned.m16n8k16.row.col.f32.f16.f16.f32 "
        "{%0,%1,%2,%3}, {%4,%5,%6,%7}, {%8,%9}, {%0,%1,%2,%3};\n"
        : "+f"(c[0]), "+f"(c[1]), "+f"(c[2]), "+f"(c[3])
        : "r"(a[0]), "r"(a[1]), "r"(a[2]), "r"(a[3]), "r"(b0), "r"(b1));
}
__device__ __forceinline__ void ldsm4(unsigned& r0, unsigned& r1, unsigned& r2,
                                      unsigned& r3, unsigned addr) {
    asm volatile("ldmatrix.sync.aligned.m8n8.x4.shared.b16 {%0,%1,%2,%3}, [%4];"
                 : "=r"(r0), "=r"(r1), "=r"(r2), "=r"(r3) : "r"(addr));
}

// smem swizzles (float units) for the tf32 GEMM
__device__ __forceinline__ int asw(int m, int k)    { return m * 32  + (k ^ ((m & 7) << 2)); }
__device__ __forceinline__ int bsw128(int k, int n) { return k * 128 + (n ^ ((k & 3) << 3)); }
__device__ __forceinline__ void cvt4(float* p) {
    *reinterpret_cast<float4*>(p) = tf32f4(*reinterpret_cast<float4*>(p));
}

// pack 8 floats -> 8 fp16 in a uint4
__device__ __forceinline__ uint4 pack8h(const float* f) {
    uint4 r;
    __half2 h;
    h = __floats2half2_rn(f[0], f[1]); r.x = *reinterpret_cast<unsigned*>(&h);
    h = __floats2half2_rn(f[2], f[3]); r.y = *reinterpret_cast<unsigned*>(&h);
    h = __floats2half2_rn(f[4], f[5]); r.z = *reinterpret_cast<unsigned*>(&h);
    h = __floats2half2_rn(f[6], f[7]); r.w = *reinterpret_cast<unsigned*>(&h);
    return r;
}

// ============ fp16 value GEMM: C[M,256] = A[M,256] @ Bt^T + bias ===========
// Bt = W_val^T fp16, [n=256][k=256].  BM=128, BN=128, BK=32, 256 threads,
// 8 warps, warp tile 32x64, m16n8k16, ldmatrix fragments.
// Smem tile: 128 rows x 64B (32 halves), 16B-chunk swizzle c ^= (row>>1)&3.
// Conflict-free for STS.128, cp.async, and all LDSM phases.
__global__ __launch_bounds__(256, 2) void gemm_f16_val(
    const float* __restrict__ A, const __half* __restrict__ Bt,
    const float* __restrict__ bias, float* __restrict__ C)
{
    extern __shared__ char smem[];
    char* Asm = smem;                       // [2][8192]
    char* Bsm = smem + 16384;               // [2][8192]
    const unsigned sA = (unsigned)__cvta_generic_to_shared(Asm);
    const unsigned sB = (unsigned)__cvta_generic_to_shared(Bsm);

    const int tid = threadIdx.x;
    const int wid = tid >> 5, lane = tid & 31;
    const int g = lane >> 2, t4 = lane & 3;
    const int bm = blockIdx.y * 128;
    const int bn = blockIdx.x * 128;
    const int warp_m = (wid >> 1) * 32;     // 0,32,64,96
    const int warp_n = (wid & 1) * 64;      // 0,64

    // ldmatrix lane geometry
    const int a_row0 = warp_m + (lane & 7) + ((lane >> 3) & 1) * 8;  // +16 per mi
    const int a_csel = lane >> 4;            // +0/+1 chunk
    const int a_rsw  = (a_row0 >> 1) & 3;    // invariant under +16
    const int b_sel  = lane >> 3;
    const int b_row0 = warp_n + (b_sel >> 1) * 8 + (lane & 7);       // +16 per j
    const int b_cadd = b_sel & 1;
    const int b_rsw  = (b_row0 >> 1) & 3;

    // staging coords: 2 threads per row, 16 halves (2 chunks) each
    const int lm = tid >> 1;
    const int cb = (tid & 1) * 2;            // chunk base 0 or 2
    const int lk = (tid & 1) * 16;           // half offset

    float4 ra[4];

    auto ldgA = [&](int t) {
        const float* Ag = A + (size_t)(bm + lm) * 256 + t * 32 + lk;
#pragma unroll
        for (int p = 0; p < 4; p++)
            ra[p] = *reinterpret_cast<const float4*>(Ag + p * 4);
    };
    auto stsA = [&](int s) {
        const int sw = (lm >> 1) & 3;
        char* base = Asm + s * 8192 + lm * 64;
        *reinterpret_cast<uint4*>(base + (((cb)     ^ sw) << 4)) = pack8h(&ra[0].x);
        *reinterpret_cast<uint4*>(base + (((cb + 1) ^ sw) << 4)) = pack8h(&ra[2].x);
    };
    auto cpB = [&](int t, int s) {
        const __half* Bg = Bt + (size_t)(bn + lm) * 256 + t * 32 + cb * 8;
        const int sw = (lm >> 1) & 3;
        unsigned base = sB + s * 8192 + lm * 64;
        cp16(base + (((cb)     ^ sw) << 4), Bg);
        cp16(base + (((cb + 1) ^ sw) << 4), Bg + 8);
        asm volatile("cp.async.commit_group;\n");
    };

    float c[2][8][4];
#pragma unroll
    for (int mi = 0; mi < 2; mi++)
#pragma unroll
        for (int nj = 0; nj < 8; nj++)
#pragma unroll
            for (int r = 0; r < 4; r++) c[mi][nj][r] = 0.f;

    // ---- prologue ----
    cpB(0, 0);
    ldgA(0);
    stsA(0);

#pragma unroll 1
    for (int t = 0; t < 8; t++) {
        if (t + 1 < 8) {
            ldgA(t + 1);                      // LDG early
            cpB(t + 1, (t + 1) & 1);
            asm volatile("cp.async.wait_group 1;\n" ::: "memory");
        } else {
            asm volatile("cp.async.wait_group 0;\n" ::: "memory");
        }
        __syncthreads();

        const unsigned aB = sA + (t & 1) * 8192;
        const unsigned bB = sB + (t & 1) * 8192;

#pragma unroll
        for (int kk = 0; kk < 2; kk++) {      // chunks 2*kk, 2*kk+1  (k 16 per iter)
            const int c0 = 2 * kk;
            unsigned a[2][4];
#pragma unroll
            for (int mi = 0; mi < 2; mi++) {
                const int row = a_row0 + mi * 16;
                ldsm4(a[mi][0], a[mi][1], a[mi][2], a[mi][3],
                      aB + row * 64 + (((c0 + a_csel) ^ a_rsw) << 4));
            }
            unsigned b[4][4];
#pragma unroll
            for (int j = 0; j < 4; j++) {
                const int nrow = b_row0 + j * 16;
                ldsm4(b[j][0], b[j][1], b[j][2], b[j][3],
                      bB + nrow * 64 + (((c0 + b_cadd) ^ b_rsw) << 4));
            }
#pragma unroll
            for (int j = 0; j < 4; j++) {
                mma_f16(c[0][2 * j],     a[0], b[j][0], b[j][1]);
                mma_f16(c[1][2 * j],     a[1], b[j][0], b[j][1]);
                mma_f16(c[0][2 * j + 1], a[0], b[j][2], b[j][3]);
                mma_f16(c[1][2 * j + 1], a[1], b[j][2], b[j][3]);
            }
        }

        if (t + 1 < 8) {
            __syncthreads();
            stsA((t + 1) & 1);
        }
    }

    // ---- epilogue: bias + float2 stores ----
#pragma unroll
    for (int mi = 0; mi < 2; mi++) {
        const int r0 = bm + warp_m + mi * 16 + g;
#pragma unroll
        for (int nj = 0; nj < 8; nj++) {
            const int col = bn + warp_n + nj * 8 + 2 * t4;
            const float bx = bias[col], by = bias[col + 1];
            float2 v0 = make_float2(c[mi][nj][0] + bx, c[mi][nj][1] + by);
            float2 v1 = make_float2(c[mi][nj][2] + bx, c[mi][nj][3] + by);
            *reinterpret_cast<float2*>(C + (size_t)r0 * 256 + col) = v0;
            *reinterpret_cast<float2*>(C + (size_t)(r0 + 8) * 256 + col) = v1;
        }
    }
}

// ---------------- W_val transpose + fp16 convert (tiny prep) ---------------
__global__ void transpose_half(const float* __restrict__ W, __half* __restrict__ Wt)
{
    int i = blockIdx.x * blockDim.x + threadIdx.x;   // i = n*256 + k
    if (i < DM * DM) {
        int n = i >> 8, k = i & 255;
        Wt[i] = __float2half(W[k * DM + n]);
    }
}

// ============ guarded TF32 GEMM (q-side / out projections) ================
__global__ __launch_bounds__(256, 2) void gemm_tf32_g(
    const float* __restrict__ A, const float* __restrict__ B,
    const float* __restrict__ bias, float* __restrict__ C,
    int M, int N, int K)
{
    extern __shared__ float sm[];
    float* As = sm;          // [2][4096]
    float* Bs = sm + 8192;   // [2][4096]

    const int tid = threadIdx.x;
    const int wid = tid >> 5, lane = tid & 31;
    const int g = lane >> 2, t4 = lane & 3;
    const int bm = blockIdx.y * 128;
    const int bn = blockIdx.x * 128;
    const int warp_m = (wid >> 1) * 32;
    const int warp_n = (wid & 1) * 64;

    const unsigned smA = (unsigned)__cvta_generic_to_shared(As);
    const unsigned smB = (unsigned)__cvta_generic_to_shared(Bs);

    float c[2][8][4];
#pragma unroll
    for (int mi = 0; mi < 2; mi++)
#pragma unroll
        for (int nj = 0; nj < 8; nj++)
#pragma unroll
            for (int r = 0; r < 4; r++) c[mi][nj][r] = 0.f;

    const int nT = K / 32;

    auto load_stage = [&](int t, int s) {
#pragma unroll
        for (int p = 0; p < 4; p++) {
            int ci = p * 256 + tid;
            int m = ci >> 3, k4 = (ci & 7) << 2;
            int gr = bm + m; if (gr > M - 1) gr = M - 1;
            cp16(smA + (unsigned)(s * 4096 + asw(m, k4)) * 4u,
                 A + (size_t)gr * K + t * 32 + k4);
        }
#pragma unroll
        for (int p = 0; p < 4; p++) {
            int ci = p * 256 + tid;
            int k = ci >> 5, n4 = (ci & 31) << 2;
            int gc = bn + n4; if (gc > N - 4) gc = N - 4;
            cp16(smB + (unsigned)(s * 4096 + bsw128(k, n4)) * 4u,
                 B + (size_t)(t * 32 + k) * N + gc);
        }
    };

    load_stage(0, 0);
    asm volatile("cp.async.commit_group;\n");

#pragma unroll 1
    for (int t = 0; t < nT; t++) {
        if (t + 1 < nT) {
            load_stage(t + 1, (t + 1) & 1);
            asm volatile("cp.async.commit_group;\n");
            asm volatile("cp.async.wait_group 1;\n");
        } else {
            asm volatile("cp.async.wait_group 0;\n");
        }
        __syncthreads();

        float* as = As + (t & 1) * 4096;
        float* bs = Bs + (t & 1) * 4096;

#pragma unroll
        for (int p = 0; p < 4; p++) cvt4(as + (p * 256 + tid) * 4);
#pragma unroll
        for (int p = 0; p < 4; p++) cvt4(bs + (p * 256 + tid) * 4);
        __syncthreads();

#pragma unroll
        for (int kk = 0; kk < 32; kk += 8) {
            const int kA = kk + t4;
            unsigned a[2][4];
#pragma unroll
            for (int mi = 0; mi < 2; mi++) {
                const int r0 = warp_m + mi * 16 + g;
                const int r1 = r0 + 8;
                a[mi][0] = __float_as_uint(as[asw(r0, kA)]);
                a[mi][1] = __float_as_uint(as[asw(r1, kA)]);
                a[mi][2] = __float_as_uint(as[asw(r0, kA + 4)]);
                a[mi][3] = __float_as_uint(as[asw(r1, kA + 4)]);
            }
#pragma unroll
            for (int nj = 0; nj < 8; nj++) {
                const int col = warp_n + nj * 8 + g;
                unsigned b0 = __float_as_uint(bs[bsw128(kA, col)]);
                unsigned b1 = __float_as_uint(bs[bsw128(kA + 4, col)]);
                mma_tf32(c[0][nj], a[0], b0, b1);
                mma_tf32(c[1][nj], a[1], b0, b1);
            }
        }
        __syncthreads();
    }

#pragma unroll
    for (int mi = 0; mi < 2; mi++) {
        const int r0 = bm + warp_m + mi * 16 + g;
#pragma unroll
        for (int nj = 0; nj < 8; nj++) {
            const int col = bn + warp_n + nj * 8 + 2 * t4;
            if (col + 1 < N) {
                const float bx = bias[col], by = bias[col + 1];
                if (r0 < M) {
                    float2 v0 = make_float2(c[mi][nj][0] + bx, c[mi][nj][1] + by);
                    *reinterpret_cast<float2*>(C + (size_t)r0 * N + col) = v0;
                }
                if (r0 + 8 < M) {
                    float2 v1 = make_float2(c[mi][nj][2] + bx, c[mi][nj][3] + by);
                    *reinterpret_cast<float2*>(C + (size_t)(r0 + 8) * N + col) = v1;
                }
            }
        }
    }
}

// ---------------- concat W_off|W_attn --------------------------------------
__global__ void concat_w(const float* __restrict__ W_off, const float* __restrict__ b_off,
                         const float* __restrict__ W_attn, const float* __restrict__ b_attn,
                         float* __restrict__ Wcat, float* __restrict__ bcat)
{
    int i = blockIdx.x * blockDim.x + threadIdx.x;
    if (i < DM * QS) {
        int r = i / QS, col = i % QS;
        Wcat[i] = (col < NOFF) ? W_off[r * NOFF + col] : W_attn[r * NATT + col - NOFF];
    }
    if (i < QS)
        bcat[i] = (i < NOFF) ? b_off[i] : b_attn[i - NOFF];
}

// ---------------- sampling: one warp per (b, q, h) ------------------------
__global__ __launch_bounds__(256) void msda_sample(
    const float* __restrict__ refp_g,   // [BS, NQ, NL, 2]
    const float* __restrict__ qproj_g,  // [BS, NQ, QS]  (off | att)
    const float* __restrict__ value_g,  // [BS, SUMHW, DM]
    float* __restrict__ acc_g)          // [BS, NQ, DM]
{
    const int gwarp = (blockIdx.x * blockDim.x + threadIdx.x) >> 5;
    const int lane  = threadIdx.x & 31;
    if (gwarp >= BS * NQ * NH) return;

    const int h  = gwarp & (NH - 1);
    const int bq = gwarp >> 3;
    const int b  = bq / NQ;

    const float* att = qproj_g + (size_t)bq * QS + NOFF + h * (NL * NP);
    float w[NL * NP];
    float mx = -INFINITY;
#pragma unroll
    for (int i = 0; i < NL * NP; i++) { w[i] = att[i]; mx = fmaxf(mx, w[i]); }
    float sum = 0.f;
#pragma unroll
    for (int i = 0; i < NL * NP; i++) { w[i] = expf(w[i] - mx); sum += w[i]; }
    const float inv = 1.f / sum;
#pragma unroll
    for (int i = 0; i < NL * NP; i++) w[i] *= inv;

    const float* off = qproj_g + (size_t)bq * QS + h * (NL * NP * 2);
    const float* rp  = refp_g + (size_t)bq * (NL * 2);

    const int d = h * DH + lane;
    const float* vb = value_g + (size_t)b * SUMHW * DM + d;

    const int Hs[NL] = {128, 64, 32};
    const int Ws[NL] = {128, 64, 32};
    const int St[NL] = {0, 16384, 20480};

    float a = 0.f;
#pragma unroll
    for (int l = 0; l < NL; l++) {
        const int Wl = Ws[l], Hl = Hs[l], st = St[l];
        const float rx = rp[l * 2 + 0] * (float)Wl;
        const float ry = rp[l * 2 + 1] * (float)Hl;
#pragma unroll
        for (int p = 0; p < NP; p++) {
            const float px = rx + off[l * (NP * 2) + p * 2 + 0] - 0.5f;
            const float py = ry + off[l * (NP * 2) + p * 2 + 1] - 0.5f;
            const float fx = floorf(px), fy = floorf(py);
            const float lx = px - fx, ly = py - fy;
            const int x0 = (int)fx, y0 = (int)fy;
            const float aw = w[l * NP + p];

            const float w00 = (1.f - lx) * (1.f - ly);
            const float w10 = lx * (1.f - ly);
            const float w01 = (1.f - lx) * ly;
            const float w11 = lx * ly;

            float s = 0.f;
            if (x0 >= 0 && x0 < Wl && y0 >= 0 && y0 < Hl)
                s = fmaf(w00, vb[(size_t)(st + y0 * Wl + x0) * DM], s);
            if (x0 + 1 >= 0 && x0 + 1 < Wl && y0 >= 0 && y0 < Hl)
                s = fmaf(w10, vb[(size_t)(st + y0 * Wl + x0 + 1) * DM], s);
            if (x0 >= 0 && x0 < Wl && y0 + 1 >= 0 && y0 + 1 < Hl)
                s = fmaf(w01, vb[(size_t)(st + (y0 + 1) * Wl + x0) * DM], s);
            if (x0 + 1 >= 0 && x0 + 1 < Wl && y0 + 1 >= 0 && y0 + 1 < Hl)
                s = fmaf(w11, vb[(size_t)(st + (y0 + 1) * Wl + x0 + 1) * DM], s);
            a = fmaf(aw, s, a);
        }
    }
    acc_g[(size_t)bq * DM + d] = a;
}

// ---------------- launch ---------------------------------------------------
extern "C" void kernel_launch(void* const* d_in, const int* in_sizes, int n_in,
                              void* d_out, int out_size)
{
    const float* query  = (const float*)d_in[0];
    const float* refpts = (const float*)d_in[1];
    const float* inflat = (const float*)d_in[2];
    const float* W_off  = (const float*)d_in[5];
    const float* b_off  = (const float*)d_in[6];
    const float* W_attn = (const float*)d_in[7];
    const float* b_attn = (const float*)d_in[8];
    const float* W_val  = (const float*)d_in[9];
    const float* b_val  = (const float*)d_in[10];
    const float* W_out  = (const float*)d_in[11];
    const float* b_out  = (const float*)d_in[12];
    float* out = (float*)d_out;

    float *value, *qproj, *acc, *wcat, *bcat;
    __half* wvalT;
    cudaGetSymbolAddress((void**)&value, g_value);
    cudaGetSymbolAddress((void**)&qproj, g_qproj);
    cudaGetSymbolAddress((void**)&acc,   g_acc);
    cudaGetSymbolAddress((void**)&wcat,  g_wcat);
    cudaGetSymbolAddress((void**)&bcat,  g_bcat);
    cudaGetSymbolAddress((void**)&wvalT, g_wvalT_h);

    const int MQ = BS * NQ;          // 7200
    const int MV = BS * SUMHW;       // 172032

    const int smem_g = 2 * 2 * 4096 * (int)sizeof(float);        // 64 KB
    const int smem_v = 32768;                                    // 32 KB
    cudaFuncSetAttribute(gemm_tf32_g,  cudaFuncAttributeMaxDynamicSharedMemorySize, smem_g);
    cudaFuncSetAttribute(gemm_f16_val, cudaFuncAttributeMaxDynamicSharedMemorySize, smem_v);

    // 0) weight prep (tiny)
    concat_w<<<(DM * QS + 255) / 256, 256>>>(W_off, b_off, W_attn, b_attn, wcat, bcat);
    transpose_half<<<(DM * DM + 255) / 256, 256>>>(W_val, wvalT);

    // 1) fused q projection: [7200,256] @ [256,288] -> qproj (off | att)
    gemm_tf32_g<<<dim3(3, (MQ + 127) / 128), 256, smem_g>>>(
        query, wcat, bcat, qproj, MQ, QS, DM);

    // 2) value projection (fp16 tensor cores + ldmatrix): [172032,256] @ [256,256]
    gemm_f16_val<<<dim3(2, MV / 128), 256, smem_v>>>(inflat, wvalT, b_val, value);

    // 3) sampling
    {
        const int warps = BS * NQ * NH;
        const int blocks = (warps * 32 + 255) / 256;
        msda_sample<<<blocks, 256>>>(refpts, qproj, value, acc);
    }

    // 4) output projection: [7200,256] @ [256,256] -> d_out
    gemm_tf32_g<<<dim3(2, (MQ + 127) / 128), 256, smem_g>>>(
        acc, W_out, b_out, out, MQ, DM, DM);
}

// round 11
// speedup vs baseline: 3.5709x; 1.0369x over previous
#include <cuda_runtime.h>
#include <cuda_fp16.h>
#include <math.h>

// ---------------- problem constants ----------------
#define BS 8
#define NQ 900
#define DM 256
#define NH 8
#define NL 3
#define NP 4
#define DH 32
#define SUMHW 21504           // 128*128 + 64*64 + 32*32
#define NOFF 192              // NH*NL*NP*2
#define NATT 96               // NH*NL*NP
#define QS  (NOFF + NATT)     // 288

// ---------------- scratch ----------------
__device__ float  g_value[(size_t)BS * SUMHW * DM];   // 176 MB
__device__ float  g_qproj[(size_t)BS * NQ * QS];      // 8.3 MB
__device__ float  g_acc[(size_t)BS * NQ * DM];
__device__ float  g_wcat[DM * QS];
__device__ float  g_bcat[QS];
__device__ __half g_wvalT_h[DM * DM];                 // W_val^T in fp16, [n][k]

// ---------------- ptx helpers ----------------
__device__ __forceinline__ void cp16(unsigned dst, const void* src) {
    asm volatile("cp.async.cg.shared.global [%0], [%1], 16;\n" :: "r"(dst), "l"(src));
}
__device__ __forceinline__ float tf32f(float x) {
    unsigned u;
    asm("cvt.rna.tf32.f32 %0, %1;\n" : "=r"(u) : "f"(x));
    return __uint_as_float(u);
}
__device__ __forceinline__ float4 tf32f4(float4 v) {
    v.x = tf32f(v.x); v.y = tf32f(v.y); v.z = tf32f(v.z); v.w = tf32f(v.w);
    return v;
}
__device__ __forceinline__ void mma_tf32(float c[4], const unsigned a[4],
                                         unsigned b0, unsigned b1) {
    asm volatile(
        "mma.sync.aligned.m16n8k8.row.col.f32.tf32.tf32.f32 "
        "{%0,%1,%2,%3}, {%4,%5,%6,%7}, {%8,%9}, {%0,%1,%2,%3};\n"
        : "+f"(c[0]), "+f"(c[1]), "+f"(c[2]), "+f"(c[3])
        : "r"(a[0]), "r"(a[1]), "r"(a[2]), "r"(a[3]), "r"(b0), "r"(b1));
}
__device__ __forceinline__ void mma_f16(float c[4], const unsigned a[4],
                                        unsigned b0, unsigned b1) {
    asm volatile(
        "mma.sync.aligned.m16n8k16.row.col.f32.f16.f16.f32 "
        "{%0,%1,%2,%3}, {%4,%5,%6,%7}, {%8,%9}, {%0,%1,%2,%3};\n"
        : "+f"(c[0]), "+f"(c[1]), "+f"(c[2]), "+f"(c[3])
        : "r"(a[0]), "r"(a[1]), "r"(a[2]), "r"(a[3]), "r"(b0), "r"(b1));
}
__device__ __forceinline__ void ldsm4(unsigned& r0, unsigned& r1, unsigned& r2,
                                      unsigned& r3, unsigned addr) {
    asm volatile("ldmatrix.sync.aligned.m8n8.x4.shared.b16 {%0,%1,%2,%3}, [%4];"
                 : "=r"(r0), "=r"(r1), "=r"(r2), "=r"(r3) : "r"(addr));
}

// smem swizzles (float units) for the tf32 GEMM
__device__ __forceinline__ int asw(int m, int k)    { return m * 32  + (k ^ ((m & 7) << 2)); }
__device__ __forceinline__ int bsw128(int k, int n) { return k * 128 + (n ^ ((k & 3) << 3)); }
__device__ __forceinline__ void cvt4(float* p) {
    *reinterpret_cast<float4*>(p) = tf32f4(*reinterpret_cast<float4*>(p));
}

// pack 8 floats -> 8 fp16 in a uint4
__device__ __forceinline__ uint4 pack8h(const float* f) {
    uint4 r;
    __half2 h;
    h = __floats2half2_rn(f[0], f[1]); r.x = *reinterpret_cast<unsigned*>(&h);
    h = __floats2half2_rn(f[2], f[3]); r.y = *reinterpret_cast<unsigned*>(&h);
    h = __floats2half2_rn(f[4], f[5]); r.z = *reinterpret_cast<unsigned*>(&h);
    h = __floats2half2_rn(f[6], f[7]); r.w = *reinterpret_cast<unsigned*>(&h);
    return r;
}

// ============ fp16 value GEMM v3: BM=128, BN=256, warp tile 64x64 ==========
// C[M,256] = A[M,256] @ Bt^T + bias.  8 warps (2m x 4n), m16n8k16 + ldmatrix.
// Smem rows of 64B (32 halves), 16B-chunk swizzle c ^= (row>>1)&3.
__global__ __launch_bounds__(256) void gemm_f16_val3(
    const float* __restrict__ A, const __half* __restrict__ Bt,
    const float* __restrict__ bias, float* __restrict__ C)
{
    extern __shared__ char smem[];
    char* Asm = smem;                        // [2][8192]   (128 x 32 halves)
    char* Bsm = smem + 16384;                // [2][16384]  (256 x 32 halves)
    const unsigned sA = (unsigned)__cvta_generic_to_shared(Asm);
    const unsigned sB = (unsigned)__cvta_generic_to_shared(Bsm);

    const int tid = threadIdx.x;
    const int wid = tid >> 5, lane = tid & 31;
    const int g = lane >> 2, t4 = lane & 3;
    const int bm = blockIdx.x * 128;
    const int warp_m = (wid >> 2) * 64;      // 0,64
    const int warp_n = (wid & 3) * 64;       // 0,64,128,192

    // ldmatrix lane geometry
    const int a_row0 = warp_m + (lane & 7) + ((lane >> 3) & 1) * 8;  // +16 per mi
    const int a_csel = lane >> 4;
    const int a_rsw  = (a_row0 >> 1) & 3;    // invariant under +16
    const int b_sel  = lane >> 3;
    const int b_row0 = warp_n + (b_sel >> 1) * 8 + (lane & 7);       // +16 per j
    const int b_cadd = b_sel & 1;
    const int b_rsw  = (b_row0 >> 1) & 3;

    // A staging: 2 threads per row, 16 halves each
    const int lm = tid >> 1;
    const int cb = (tid & 1) * 2;
    const int lk = (tid & 1) * 16;
    // B staging: 1 thread per row (256 rows), 4 chunks each
    const int br  = tid;
    const int bsw = (br >> 1) & 3;

    float4 ra[4];

    auto ldgA = [&](int t) {
        const float* Ag = A + (size_t)(bm + lm) * 256 + t * 32 + lk;
#pragma unroll
        for (int p = 0; p < 4; p++)
            ra[p] = *reinterpret_cast<const float4*>(Ag + p * 4);
    };
    auto stsA = [&](int s) {
        const int sw = (lm >> 1) & 3;
        char* base = Asm + s * 8192 + lm * 64;
        *reinterpret_cast<uint4*>(base + (((cb)     ^ sw) << 4)) = pack8h(&ra[0].x);
        *reinterpret_cast<uint4*>(base + (((cb + 1) ^ sw) << 4)) = pack8h(&ra[2].x);
    };
    auto cpB = [&](int t, int s) {
        const __half* Bg = Bt + (size_t)br * 256 + t * 32;
        unsigned base = sB + s * 16384 + br * 64;
#pragma unroll
        for (int c = 0; c < 4; c++)
            cp16(base + ((c ^ bsw) << 4), Bg + c * 8);
        asm volatile("cp.async.commit_group;\n");
    };

    float c[4][8][4];
#pragma unroll
    for (int mi = 0; mi < 4; mi++)
#pragma unroll
        for (int nj = 0; nj < 8; nj++)
#pragma unroll
            for (int r = 0; r < 4; r++) c[mi][nj][r] = 0.f;

    // ---- prologue ----
    cpB(0, 0);
    ldgA(0);
    stsA(0);

#pragma unroll 1
    for (int t = 0; t < 8; t++) {
        if (t + 1 < 8) {
            ldgA(t + 1);
            cpB(t + 1, (t + 1) & 1);
            asm volatile("cp.async.wait_group 1;\n" ::: "memory");
        } else {
            asm volatile("cp.async.wait_group 0;\n" ::: "memory");
        }
        __syncthreads();

        const unsigned aB = sA + (t & 1) * 8192;
        const unsigned bB = sB + (t & 1) * 16384;

#pragma unroll
        for (int kk = 0; kk < 2; kk++) {
            const int c0 = 2 * kk;
            unsigned a[4][4];
#pragma unroll
            for (int mi = 0; mi < 4; mi++) {
                const int row = a_row0 + mi * 16;
                ldsm4(a[mi][0], a[mi][1], a[mi][2], a[mi][3],
                      aB + row * 64 + (((c0 + a_csel) ^ a_rsw) << 4));
            }
            unsigned b[4][4];
#pragma unroll
            for (int j = 0; j < 4; j++) {
                const int nrow = b_row0 + j * 16;
                ldsm4(b[j][0], b[j][1], b[j][2], b[j][3],
                      bB + nrow * 64 + (((c0 + b_cadd) ^ b_rsw) << 4));
            }
#pragma unroll
            for (int j = 0; j < 4; j++)
#pragma unroll
                for (int mi = 0; mi < 4; mi++) {
                    mma_f16(c[mi][2 * j],     a[mi], b[j][0], b[j][1]);
                    mma_f16(c[mi][2 * j + 1], a[mi], b[j][2], b[j][3]);
                }
        }

        if (t + 1 < 8) {
            __syncthreads();
            stsA((t + 1) & 1);
        }
    }

    // ---- epilogue: bias + float2 stores ----
#pragma unroll
    for (int mi = 0; mi < 4; mi++) {
        const int r0 = bm + warp_m + mi * 16 + g;
#pragma unroll
        for (int nj = 0; nj < 8; nj++) {
            const int col = warp_n + nj * 8 + 2 * t4;
            const float bx = bias[col], by = bias[col + 1];
            float2 v0 = make_float2(c[mi][nj][0] + bx, c[mi][nj][1] + by);
            float2 v1 = make_float2(c[mi][nj][2] + bx, c[mi][nj][3] + by);
            *reinterpret_cast<float2*>(C + (size_t)r0 * 256 + col) = v0;
            *reinterpret_cast<float2*>(C + (size_t)(r0 + 8) * 256 + col) = v1;
        }
    }
}

// ---------------- W_val transpose + fp16 convert (tiny prep) ---------------
__global__ void transpose_half(const float* __restrict__ W, __half* __restrict__ Wt)
{
    int i = blockIdx.x * blockDim.x + threadIdx.x;   // i = n*256 + k
    if (i < DM * DM) {
        int n = i >> 8, k = i & 255;
        Wt[i] = __float2half(W[k * DM + n]);
    }
}

// ============ guarded TF32 GEMM (q-side / out projections) ================
__global__ __launch_bounds__(256, 2) void gemm_tf32_g(
    const float* __restrict__ A, const float* __restrict__ B,
    const float* __restrict__ bias, float* __restrict__ C,
    int M, int N, int K)
{
    extern __shared__ float sm[];
    float* As = sm;          // [2][4096]
    float* Bs = sm + 8192;   // [2][4096]

    const int tid = threadIdx.x;
    const int wid = tid >> 5, lane = tid & 31;
    const int g = lane >> 2, t4 = lane & 3;
    const int bm = blockIdx.y * 128;
    const int bn = blockIdx.x * 128;
    const int warp_m = (wid >> 1) * 32;
    const int warp_n = (wid & 1) * 64;

    const unsigned smA = (unsigned)__cvta_generic_to_shared(As);
    const unsigned smB = (unsigned)__cvta_generic_to_shared(Bs);

    float c[2][8][4];
#pragma unroll
    for (int mi = 0; mi < 2; mi++)
#pragma unroll
        for (int nj = 0; nj < 8; nj++)
#pragma unroll
            for (int r = 0; r < 4; r++) c[mi][nj][r] = 0.f;

    const int nT = K / 32;

    auto load_stage = [&](int t, int s) {
#pragma unroll
        for (int p = 0; p < 4; p++) {
            int ci = p * 256 + tid;
            int m = ci >> 3, k4 = (ci & 7) << 2;
            int gr = bm + m; if (gr > M - 1) gr = M - 1;
            cp16(smA + (unsigned)(s * 4096 + asw(m, k4)) * 4u,
                 A + (size_t)gr * K + t * 32 + k4);
        }
#pragma unroll
        for (int p = 0; p < 4; p++) {
            int ci = p * 256 + tid;
            int k = ci >> 5, n4 = (ci & 31) << 2;
            int gc = bn + n4; if (gc > N - 4) gc = N - 4;
            cp16(smB + (unsigned)(s * 4096 + bsw128(k, n4)) * 4u,
                 B + (size_t)(t * 32 + k) * N + gc);
        }
    };

    load_stage(0, 0);
    asm volatile("cp.async.commit_group;\n");

#pragma unroll 1
    for (int t = 0; t < nT; t++) {
        if (t + 1 < nT) {
            load_stage(t + 1, (t + 1) & 1);
            asm volatile("cp.async.commit_group;\n");
            asm volatile("cp.async.wait_group 1;\n");
        } else {
            asm volatile("cp.async.wait_group 0;\n");
        }
        __syncthreads();

        float* as = As + (t & 1) * 4096;
        float* bs = Bs + (t & 1) * 4096;

#pragma unroll
        for (int p = 0; p < 4; p++) cvt4(as + (p * 256 + tid) * 4);
#pragma unroll
        for (int p = 0; p < 4; p++) cvt4(bs + (p * 256 + tid) * 4);
        __syncthreads();

#pragma unroll
        for (int kk = 0; kk < 32; kk += 8) {
            const int kA = kk + t4;
            unsigned a[2][4];
#pragma unroll
            for (int mi = 0; mi < 2; mi++) {
                const int r0 = warp_m + mi * 16 + g;
                const int r1 = r0 + 8;
                a[mi][0] = __float_as_uint(as[asw(r0, kA)]);
                a[mi][1] = __float_as_uint(as[asw(r1, kA)]);
                a[mi][2] = __float_as_uint(as[asw(r0, kA + 4)]);
                a[mi][3] = __float_as_uint(as[asw(r1, kA + 4)]);
            }
#pragma unroll
            for (int nj = 0; nj < 8; nj++) {
                const int col = warp_n + nj * 8 + g;
                unsigned b0 = __float_as_uint(bs[bsw128(kA, col)]);
                unsigned b1 = __float_as_uint(bs[bsw128(kA + 4, col)]);
                mma_tf32(c[0][nj], a[0], b0, b1);
                mma_tf32(c[1][nj], a[1], b0, b1);
            }
        }
        __syncthreads();
    }

#pragma unroll
    for (int mi = 0; mi < 2; mi++) {
        const int r0 = bm + warp_m + mi * 16 + g;
#pragma unroll
        for (int nj = 0; nj < 8; nj++) {
            const int col = bn + warp_n + nj * 8 + 2 * t4;
            if (col + 1 < N) {
                const float bx = bias[col], by = bias[col + 1];
                if (r0 < M) {
                    float2 v0 = make_float2(c[mi][nj][0] + bx, c[mi][nj][1] + by);
                    *reinterpret_cast<float2*>(C + (size_t)r0 * N + col) = v0;
                }
                if (r0 + 8 < M) {
                    float2 v1 = make_float2(c[mi][nj][2] + bx, c[mi][nj][3] + by);
                    *reinterpret_cast<float2*>(C + (size_t)(r0 + 8) * N + col) = v1;
                }
            }
        }
    }
}

// ---------------- concat W_off|W_attn --------------------------------------
__global__ void concat_w(const float* __restrict__ W_off, const float* __restrict__ b_off,
                         const float* __restrict__ W_attn, const float* __restrict__ b_attn,
                         float* __restrict__ Wcat, float* __restrict__ bcat)
{
    int i = blockIdx.x * blockDim.x + threadIdx.x;
    if (i < DM * QS) {
        int r = i / QS, col = i % QS;
        Wcat[i] = (col < NOFF) ? W_off[r * NOFF + col] : W_attn[r * NATT + col - NOFF];
    }
    if (i < QS)
        bcat[i] = (i < NOFF) ? b_off[i] : b_attn[i - NOFF];
}

// ---------------- sampling v2: lane-parallel point precompute --------------
// Warp per (b,q,h).  Lanes 0-11 compute softmax + coords for one point each,
// stash (4 masks, 4 clamped indices) in smem; then all 32 lanes gather.
__global__ __launch_bounds__(256) void msda_sample2(
    const float* __restrict__ refp_g,   // [BS, NQ, NL, 2]
    const float* __restrict__ qproj_g,  // [BS, NQ, QS]  (off | att)
    const float* __restrict__ value_g,  // [BS, SUMHW, DM]
    float* __restrict__ acc_g)          // [BS, NQ, DM]
{
    __shared__ float sdata[8][96];

    const int wlocal = threadIdx.x >> 5;
    const int gwarp  = (blockIdx.x * blockDim.x + threadIdx.x) >> 5;
    const int lane   = threadIdx.x & 31;
    if (gwarp >= BS * NQ * NH) return;

    const int h  = gwarp & (NH - 1);
    const int bq = gwarp >> 3;
    const int b  = bq / NQ;

    float* sp = sdata[wlocal];

    // ---- phase 1: lanes 0-11 compute one point each ----
    {
        const int i = lane;
        float v = -INFINITY;
        if (i < 12) v = qproj_g[(size_t)bq * QS + NOFF + h * 12 + i];
        float mx = v;
#pragma unroll
        for (int o = 8; o; o >>= 1) mx = fmaxf(mx, __shfl_xor_sync(0xffffffffu, mx, o, 16));
        float e = (i < 12) ? expf(v - mx) : 0.f;
        float s = e;
#pragma unroll
        for (int o = 8; o; o >>= 1) s += __shfl_xor_sync(0xffffffffu, s, o, 16);

        if (i < 12) {
            const float aw = e / s;
            const int l   = i >> 2;
            const int Dim = 128 >> l;                    // 128,64,32
            const int st  = (l == 0) ? 0 : (l == 1) ? 16384 : 20480;
            const float ref_x = refp_g[(size_t)bq * (NL * 2) + 2 * l];
            const float ref_y = refp_g[(size_t)bq * (NL * 2) + 2 * l + 1];
            const float ox = qproj_g[(size_t)bq * QS + h * 24 + 2 * i];
            const float oy = qproj_g[(size_t)bq * QS + h * 24 + 2 * i + 1];

            const float px = ref_x * (float)Dim + ox - 0.5f;
            const float py = ref_y * (float)Dim + oy - 0.5f;
            const float fx = floorf(px), fy = floorf(py);
            const float lx = px - fx, ly = py - fy;
            const int x0 = (int)fx, y0 = (int)fy;

            const bool vx0 = ((unsigned)x0       < (unsigned)Dim);
            const bool vx1 = ((unsigned)(x0 + 1) < (unsigned)Dim);
            const bool vy0 = ((unsigned)y0       < (unsigned)Dim);
            const bool vy1 = ((unsigned)(y0 + 1) < (unsigned)Dim);

            const int cx0 = min(max(x0, 0), Dim - 1);
            const int cx1 = min(max(x0 + 1, 0), Dim - 1);
            const int cy0 = min(max(y0, 0), Dim - 1);
            const int cy1 = min(max(y0 + 1, 0), Dim - 1);

            sp[i * 8 + 0] = (vx0 && vy0) ? aw * (1.f - lx) * (1.f - ly) : 0.f;
            sp[i * 8 + 1] = (vx1 && vy0) ? aw * lx * (1.f - ly) : 0.f;
            sp[i * 8 + 2] = (vx0 && vy1) ? aw * (1.f - lx) * ly : 0.f;
            sp[i * 8 + 3] = (vx1 && vy1) ? aw * lx * ly : 0.f;
            sp[i * 8 + 4] = __int_as_float((st + cy0 * Dim + cx0) * DM);
            sp[i * 8 + 5] = __int_as_float((st + cy0 * Dim + cx1) * DM);
            sp[i * 8 + 6] = __int_as_float((st + cy1 * Dim + cx0) * DM);
            sp[i * 8 + 7] = __int_as_float((st + cy1 * Dim + cx1) * DM);
        }
    }
    __syncwarp();

    // ---- phase 2: all lanes gather 12 points x 4 taps ----
    const float* vb = value_g + (size_t)b * SUMHW * DM + h * DH + lane;
    float a0 = 0.f, a1 = 0.f;
#pragma unroll
    for (int i = 0; i < 12; i++) {
        const float m00 = sp[i * 8 + 0];
        const float m10 = sp[i * 8 + 1];
        const float m01 = sp[i * 8 + 2];
        const float m11 = sp[i * 8 + 3];
        const int i00 = __float_as_int(sp[i * 8 + 4]);
        const int i10 = __float_as_int(sp[i * 8 + 5]);
        const int i01 = __float_as_int(sp[i * 8 + 6]);
        const int i11 = __float_as_int(sp[i * 8 + 7]);
        a0 = fmaf(m00, vb[i00], a0);
        a1 = fmaf(m10, vb[i10], a1);
        a0 = fmaf(m01, vb[i01], a0);
        a1 = fmaf(m11, vb[i11], a1);
    }
    acc_g[(size_t)bq * DM + h * DH + lane] = a0 + a1;
}

// ---------------- launch ---------------------------------------------------
extern "C" void kernel_launch(void* const* d_in, const int* in_sizes, int n_in,
                              void* d_out, int out_size)
{
    const float* query  = (const float*)d_in[0];
    const float* refpts = (const float*)d_in[1];
    const float* inflat = (const float*)d_in[2];
    const float* W_off  = (const float*)d_in[5];
    const float* b_off  = (const float*)d_in[6];
    const float* W_attn = (const float*)d_in[7];
    const float* b_attn = (const float*)d_in[8];
    const float* W_val  = (const float*)d_in[9];
    const float* b_val  = (const float*)d_in[10];
    const float* W_out  = (const float*)d_in[11];
    const float* b_out  = (const float*)d_in[12];
    float* out = (float*)d_out;

    float *value, *qproj, *acc, *wcat, *bcat;
    __half* wvalT;
    cudaGetSymbolAddress((void**)&value, g_value);
    cudaGetSymbolAddress((void**)&qproj, g_qproj);
    cudaGetSymbolAddress((void**)&acc,   g_acc);
    cudaGetSymbolAddress((void**)&wcat,  g_wcat);
    cudaGetSymbolAddress((void**)&bcat,  g_bcat);
    cudaGetSymbolAddress((void**)&wvalT, g_wvalT_h);

    const int MQ = BS * NQ;          // 7200
    const int MV = BS * SUMHW;       // 172032

    const int smem_g = 2 * 2 * 4096 * (int)sizeof(float);        // 64 KB
    const int smem_v = 49152;                                    // 48 KB
    cudaFuncSetAttribute(gemm_tf32_g,   cudaFuncAttributeMaxDynamicSharedMemorySize, smem_g);
    cudaFuncSetAttribute(gemm_f16_val3, cudaFuncAttributeMaxDynamicSharedMemorySize, smem_v);

    // 0) weight prep (tiny)
    concat_w<<<(DM * QS + 255) / 256, 256>>>(W_off, b_off, W_attn, b_attn, wcat, bcat);
    transpose_half<<<(DM * DM + 255) / 256, 256>>>(W_val, wvalT);

    // 1) fused q projection: [7200,256] @ [256,288] -> qproj (off | att)
    gemm_tf32_g<<<dim3(3, (MQ + 127) / 128), 256, smem_g>>>(
        query, wcat, bcat, qproj, MQ, QS, DM);

    // 2) value projection (fp16, warp tile 64x64): [172032,256] @ [256,256]
    gemm_f16_val3<<<MV / 128, 256, smem_v>>>(inflat, wvalT, b_val, value);

    // 3) sampling (lane-parallel precompute)
    {
        const int warps = BS * NQ * NH;
        const int blocks = (warps * 32 + 255) / 256;
        msda_sample2<<<blocks, 256>>>(refpts, qproj, value, acc);
    }

    // 4) output projection: [7200,256] @ [256,256] -> d_out
    gemm_tf32_g<<<dim3(2, (MQ + 127) / 128), 256, smem_g>>>(
        acc, W_out, b_out, out, MQ, DM, DM);
}

// round 13
// speedup vs baseline: 3.7276x; 1.0439x over previous
#include <cuda_runtime.h>
#include <cuda_fp16.h>
#include <math.h>

// ---------------- problem constants ----------------
#define BS 8
#define NQ 900
#define DM 256
#define NH 8
#define NL 3
#define NP 4
#define DH 32
#define SUMHW 21504           // 128*128 + 64*64 + 32*32
#define NOFF 192              // NH*NL*NP*2
#define NATT 96               // NH*NL*NP
#define QS  (NOFF + NATT)     // 288

// ---------------- scratch ----------------
__device__ float  g_value[(size_t)BS * SUMHW * DM];   // 176 MB
__device__ float  g_qproj[(size_t)BS * NQ * QS];      // 8.3 MB
__device__ float  g_acc[(size_t)BS * NQ * DM];
__device__ float  g_wcat[DM * QS];
__device__ float  g_bcat[QS];
__device__ __half g_wvalT_h[DM * DM];                 // W_val^T in fp16, [n][k]

// ---------------- ptx helpers ----------------
__device__ __forceinline__ void cp16(unsigned dst, const void* src) {
    asm volatile("cp.async.cg.shared.global [%0], [%1], 16;\n" :: "r"(dst), "l"(src));
}
__device__ __forceinline__ float tf32f(float x) {
    unsigned u;
    asm("cvt.rna.tf32.f32 %0, %1;\n" : "=r"(u) : "f"(x));
    return __uint_as_float(u);
}
__device__ __forceinline__ float4 tf32f4(float4 v) {
    v.x = tf32f(v.x); v.y = tf32f(v.y); v.z = tf32f(v.z); v.w = tf32f(v.w);
    return v;
}
__device__ __forceinline__ void mma_tf32(float c[4], const unsigned a[4],
                                         unsigned b0, unsigned b1) {
    asm volatile(
        "mma.sync.aligned.m16n8k8.row.col.f32.tf32.tf32.f32 "
        "{%0,%1,%2,%3}, {%4,%5,%6,%7}, {%8,%9}, {%0,%1,%2,%3};\n"
        : "+f"(c[0]), "+f"(c[1]), "+f"(c[2]), "+f"(c[3])
        : "r"(a[0]), "r"(a[1]), "r"(a[2]), "r"(a[3]), "r"(b0), "r"(b1));
}
__device__ __forceinline__ void mma_f16(float c[4], const unsigned a[4],
                                        unsigned b0, unsigned b1) {
    asm volatile(
        "mma.sync.aligned.m16n8k16.row.col.f32.f16.f16.f32 "
        "{%0,%1,%2,%3}, {%4,%5,%6,%7}, {%8,%9}, {%0,%1,%2,%3};\n"
        : "+f"(c[0]), "+f"(c[1]), "+f"(c[2]), "+f"(c[3])
        : "r"(a[0]), "r"(a[1]), "r"(a[2]), "r"(a[3]), "r"(b0), "r"(b1));
}
__device__ __forceinline__ void ldsm4(unsigned& r0, unsigned& r1, unsigned& r2,
                                      unsigned& r3, unsigned addr) {
    asm volatile("ldmatrix.sync.aligned.m8n8.x4.shared.b16 {%0,%1,%2,%3}, [%4];"
                 : "=r"(r0), "=r"(r1), "=r"(r2), "=r"(r3) : "r"(addr));
}

// smem swizzles (float units) for the tf32 GEMM
__device__ __forceinline__ int asw(int m, int k)    { return m * 32  + (k ^ ((m & 7) << 2)); }
__device__ __forceinline__ int bsw128(int k, int n) { return k * 128 + (n ^ ((k & 3) << 3)); }
__device__ __forceinline__ void cvt4(float* p) {
    *reinterpret_cast<float4*>(p) = tf32f4(*reinterpret_cast<float4*>(p));
}

// pack 8 floats -> 8 fp16 in a uint4
__device__ __forceinline__ uint4 pack8h(const float* f) {
    uint4 r;
    __half2 h;
    h = __floats2half2_rn(f[0], f[1]); r.x = *reinterpret_cast<unsigned*>(&h);
    h = __floats2half2_rn(f[2], f[3]); r.y = *reinterpret_cast<unsigned*>(&h);
    h = __floats2half2_rn(f[4], f[5]); r.z = *reinterpret_cast<unsigned*>(&h);
    h = __floats2half2_rn(f[6], f[7]); r.w = *reinterpret_cast<unsigned*>(&h);
    return r;
}

// ============ fp16 value GEMM v4: BM=128, BN=256, warp 64x64, 3-stage ======
// C[M,256] = A[M,256] @ Bt^T + bias.  8 warps (2m x 4n), m16n8k16 + ldmatrix.
// Smem rows of 64B (32 halves), 16B-chunk swizzle c ^= (row>>1)&3.
// 3 staging buffers, ONE __syncthreads per k-tile.
#define AST 8192
#define BST 16384
__global__ __launch_bounds__(256) void gemm_f16_val4(
    const float* __restrict__ A, const __half* __restrict__ Bt,
    const float* __restrict__ bias, float* __restrict__ C)
{
    extern __shared__ char smem[];
    char* Asm = smem;                        // [3][8192]   (128 x 32 halves)
    char* Bsm = smem + 3 * AST;              // [3][16384]  (256 x 32 halves)
    const unsigned sA = (unsigned)__cvta_generic_to_shared(Asm);
    const unsigned sB = (unsigned)__cvta_generic_to_shared(Bsm);

    const int tid = threadIdx.x;
    const int wid = tid >> 5, lane = tid & 31;
    const int g = lane >> 2, t4 = lane & 3;
    const int bm = blockIdx.x * 128;
    const int warp_m = (wid >> 2) * 64;      // 0,64
    const int warp_n = (wid & 3) * 64;       // 0,64,128,192

    // ldmatrix lane geometry
    const int a_row0 = warp_m + (lane & 7) + ((lane >> 3) & 1) * 8;  // +16 per mi
    const int a_csel = lane >> 4;
    const int a_rsw  = (a_row0 >> 1) & 3;    // invariant under +16
    const int b_sel  = lane >> 3;
    const int b_row0 = warp_n + (b_sel >> 1) * 8 + (lane & 7);       // +16 per j
    const int b_cadd = b_sel & 1;
    const int b_rsw  = (b_row0 >> 1) & 3;

    // A staging: 2 threads per row, 16 halves each
    const int lm = tid >> 1;
    const int cb = (tid & 1) * 2;
    const int lk = (tid & 1) * 16;
    // B staging: 1 thread per row (256 rows), 4 chunks each
    const int br  = tid;
    const int bsw = (br >> 1) & 3;

    float4 ra[4];

    auto ldgA = [&](int t) {
        const float* Ag = A + (size_t)(bm + lm) * 256 + t * 32 + lk;
#pragma unroll
        for (int p = 0; p < 4; p++)
            ra[p] = *reinterpret_cast<const float4*>(Ag + p * 4);
    };
    auto stsA = [&](int s) {
        const int sw = (lm >> 1) & 3;
        char* base = Asm + s * AST + lm * 64;
        *reinterpret_cast<uint4*>(base + (((cb)     ^ sw) << 4)) = pack8h(&ra[0].x);
        *reinterpret_cast<uint4*>(base + (((cb + 1) ^ sw) << 4)) = pack8h(&ra[2].x);
    };
    auto cpB = [&](int t, int s) {
        const __half* Bg = Bt + (size_t)br * 256 + t * 32;
        unsigned base = sB + s * BST + br * 64;
#pragma unroll
        for (int c = 0; c < 4; c++)
            cp16(base + ((c ^ bsw) << 4), Bg + c * 8);
        asm volatile("cp.async.commit_group;\n");
    };

    float c[4][8][4];
#pragma unroll
    for (int mi = 0; mi < 4; mi++)
#pragma unroll
        for (int nj = 0; nj < 8; nj++)
#pragma unroll
            for (int r = 0; r < 4; r++) c[mi][nj][r] = 0.f;

    // ---- prologue: stage 0 (A regs->smem), B groups 0 and 1 in flight ----
    ldgA(0);
    cpB(0, 0);
    cpB(1, 1);
    stsA(0);

    int sbuf = 0;                            // buffer index = t % 3
#pragma unroll 1
    for (int t = 0; t < 8; t++) {
        // B stage t complete (groups FIFO; allow 1 pending = stage t+1)
        if (t < 7) asm volatile("cp.async.wait_group 1;\n" ::: "memory");
        else       asm volatile("cp.async.wait_group 0;\n" ::: "memory");
        __syncthreads();   // publish stsA(t); all readers of reused buffers done

        const int nbuf = (sbuf + 1 < 3) ? sbuf + 1 : 0;
        const int n2buf = (nbuf + 1 < 3) ? nbuf + 1 : 0;

        if (t + 1 < 8) ldgA(t + 1);          // hide LDG under compute
        if (t + 2 < 8) cpB(t + 2, n2buf);    // buf (t+2)%3: old readers past barrier

        const unsigned aB = sA + sbuf * AST;
        const unsigned bB = sB + sbuf * BST;

#pragma unroll
        for (int kk = 0; kk < 2; kk++) {
            const int c0 = 2 * kk;
            unsigned a[4][4];
#pragma unroll
            for (int mi = 0; mi < 4; mi++) {
                const int row = a_row0 + mi * 16;
                ldsm4(a[mi][0], a[mi][1], a[mi][2], a[mi][3],
                      aB + row * 64 + (((c0 + a_csel) ^ a_rsw) << 4));
            }
            unsigned b[4][4];
#pragma unroll
            for (int j = 0; j < 4; j++) {
                const int nrow = b_row0 + j * 16;
                ldsm4(b[j][0], b[j][1], b[j][2], b[j][3],
                      bB + nrow * 64 + (((c0 + b_cadd) ^ b_rsw) << 4));
            }
#pragma unroll
            for (int j = 0; j < 4; j++)
#pragma unroll
                for (int mi = 0; mi < 4; mi++) {
                    mma_f16(c[mi][2 * j],     a[mi], b[j][0], b[j][1]);
                    mma_f16(c[mi][2 * j + 1], a[mi], b[j][2], b[j][3]);
                }
        }

        if (t + 1 < 8) stsA(nbuf);           // buf (t+1)%3: last read at t-2
        sbuf = nbuf;
    }

    // ---- epilogue: bias + float2 stores ----
#pragma unroll
    for (int mi = 0; mi < 4; mi++) {
        const int r0 = bm + warp_m + mi * 16 + g;
#pragma unroll
        for (int nj = 0; nj < 8; nj++) {
            const int col = warp_n + nj * 8 + 2 * t4;
            const float bx = bias[col], by = bias[col + 1];
            float2 v0 = make_float2(c[mi][nj][0] + bx, c[mi][nj][1] + by);
            float2 v1 = make_float2(c[mi][nj][2] + bx, c[mi][nj][3] + by);
            *reinterpret_cast<float2*>(C + (size_t)r0 * 256 + col) = v0;
            *reinterpret_cast<float2*>(C + (size_t)(r0 + 8) * 256 + col) = v1;
        }
    }
}

// ---------------- W_val transpose + fp16 convert (tiny prep) ---------------
__global__ void transpose_half(const float* __restrict__ W, __half* __restrict__ Wt)
{
    int i = blockIdx.x * blockDim.x + threadIdx.x;   // i = n*256 + k
    if (i < DM * DM) {
        int n = i >> 8, k = i & 255;
        Wt[i] = __float2half(W[k * DM + n]);
    }
}

// ============ guarded TF32 GEMM (q-side / out projections) ================
__global__ __launch_bounds__(256, 2) void gemm_tf32_g(
    const float* __restrict__ A, const float* __restrict__ B,
    const float* __restrict__ bias, float* __restrict__ C,
    int M, int N, int K)
{
    extern __shared__ float sm[];
    float* As = sm;          // [2][4096]
    float* Bs = sm + 8192;   // [2][4096]

    const int tid = threadIdx.x;
    const int wid = tid >> 5, lane = tid & 31;
    const int g = lane >> 2, t4 = lane & 3;
    const int bm = blockIdx.y * 128;
    const int bn = blockIdx.x * 128;
    const int warp_m = (wid >> 1) * 32;
    const int warp_n = (wid & 1) * 64;

    const unsigned smA = (unsigned)__cvta_generic_to_shared(As);
    const unsigned smB = (unsigned)__cvta_generic_to_shared(Bs);

    float c[2][8][4];
#pragma unroll
    for (int mi = 0; mi < 2; mi++)
#pragma unroll
        for (int nj = 0; nj < 8; nj++)
#pragma unroll
            for (int r = 0; r < 4; r++) c[mi][nj][r] = 0.f;

    const int nT = K / 32;

    auto load_stage = [&](int t, int s) {
#pragma unroll
        for (int p = 0; p < 4; p++) {
            int ci = p * 256 + tid;
            int m = ci >> 3, k4 = (ci & 7) << 2;
            int gr = bm + m; if (gr > M - 1) gr = M - 1;
            cp16(smA + (unsigned)(s * 4096 + asw(m, k4)) * 4u,
                 A + (size_t)gr * K + t * 32 + k4);
        }
#pragma unroll
        for (int p = 0; p < 4; p++) {
            int ci = p * 256 + tid;
            int k = ci >> 5, n4 = (ci & 31) << 2;
            int gc = bn + n4; if (gc > N - 4) gc = N - 4;
            cp16(smB + (unsigned)(s * 4096 + bsw128(k, n4)) * 4u,
                 B + (size_t)(t * 32 + k) * N + gc);
        }
    };

    load_stage(0, 0);
    asm volatile("cp.async.commit_group;\n");

#pragma unroll 1
    for (int t = 0; t < nT; t++) {
        if (t + 1 < nT) {
            load_stage(t + 1, (t + 1) & 1);
            asm volatile("cp.async.commit_group;\n");
            asm volatile("cp.async.wait_group 1;\n");
        } else {
            asm volatile("cp.async.wait_group 0;\n");
        }
        __syncthreads();

        float* as = As + (t & 1) * 4096;
        float* bs = Bs + (t & 1) * 4096;

#pragma unroll
        for (int p = 0; p < 4; p++) cvt4(as + (p * 256 + tid) * 4);
#pragma unroll
        for (int p = 0; p < 4; p++) cvt4(bs + (p * 256 + tid) * 4);
        __syncthreads();

#pragma unroll
        for (int kk = 0; kk < 32; kk += 8) {
            const int kA = kk + t4;
            unsigned a[2][4];
#pragma unroll
            for (int mi = 0; mi < 2; mi++) {
                const int r0 = warp_m + mi * 16 + g;
                const int r1 = r0 + 8;
                a[mi][0] = __float_as_uint(as[asw(r0, kA)]);
                a[mi][1] = __float_as_uint(as[asw(r1, kA)]);
                a[mi][2] = __float_as_uint(as[asw(r0, kA + 4)]);
                a[mi][3] = __float_as_uint(as[asw(r1, kA + 4)]);
            }
#pragma unroll
            for (int nj = 0; nj < 8; nj++) {
                const int col = warp_n + nj * 8 + g;
                unsigned b0 = __float_as_uint(bs[bsw128(kA, col)]);
                unsigned b1 = __float_as_uint(bs[bsw128(kA + 4, col)]);
                mma_tf32(c[0][nj], a[0], b0, b1);
                mma_tf32(c[1][nj], a[1], b0, b1);
            }
        }
        __syncthreads();
    }

#pragma unroll
    for (int mi = 0; mi < 2; mi++) {
        const int r0 = bm + warp_m + mi * 16 + g;
#pragma unroll
        for (int nj = 0; nj < 8; nj++) {
            const int col = bn + warp_n + nj * 8 + 2 * t4;
            if (col + 1 < N) {
                const float bx = bias[col], by = bias[col + 1];
                if (r0 < M) {
                    float2 v0 = make_float2(c[mi][nj][0] + bx, c[mi][nj][1] + by);
                    *reinterpret_cast<float2*>(C + (size_t)r0 * N + col) = v0;
                }
                if (r0 + 8 < M) {
                    float2 v1 = make_float2(c[mi][nj][2] + bx, c[mi][nj][3] + by);
                    *reinterpret_cast<float2*>(C + (size_t)(r0 + 8) * N + col) = v1;
                }
            }
        }
    }
}

// ---------------- concat W_off|W_attn --------------------------------------
__global__ void concat_w(const float* __restrict__ W_off, const float* __restrict__ b_off,
                         const float* __restrict__ W_attn, const float* __restrict__ b_attn,
                         float* __restrict__ Wcat, float* __restrict__ bcat)
{
    int i = blockIdx.x * blockDim.x + threadIdx.x;
    if (i < DM * QS) {
        int r = i / QS, col = i % QS;
        Wcat[i] = (col < NOFF) ? W_off[r * NOFF + col] : W_attn[r * NATT + col - NOFF];
    }
    if (i < QS)
        bcat[i] = (i < NOFF) ? b_off[i] : b_attn[i - NOFF];
}

// ---------------- sampling v2: lane-parallel point precompute --------------
__global__ __launch_bounds__(256) void msda_sample2(
    const float* __restrict__ refp_g,   // [BS, NQ, NL, 2]
    const float* __restrict__ qproj_g,  // [BS, NQ, QS]  (off | att)
    const float* __restrict__ value_g,  // [BS, SUMHW, DM]
    float* __restrict__ acc_g)          // [BS, NQ, DM]
{
    __shared__ float sdata[8][96];

    const int wlocal = threadIdx.x >> 5;
    const int gwarp  = (blockIdx.x * blockDim.x + threadIdx.x) >> 5;
    const int lane   = threadIdx.x & 31;
    if (gwarp >= BS * NQ * NH) return;

    const int h  = gwarp & (NH - 1);
    const int bq = gwarp >> 3;
    const int b  = bq / NQ;

    float* sp = sdata[wlocal];

    // ---- phase 1: lanes 0-11 compute one point each ----
    {
        const int i = lane;
        float v = -INFINITY;
        if (i < 12) v = qproj_g[(size_t)bq * QS + NOFF + h * 12 + i];
        float mx = v;
#pragma unroll
        for (int o = 8; o; o >>= 1) mx = fmaxf(mx, __shfl_xor_sync(0xffffffffu, mx, o, 16));
        float e = (i < 12) ? expf(v - mx) : 0.f;
        float s = e;
#pragma unroll
        for (int o = 8; o; o >>= 1) s += __shfl_xor_sync(0xffffffffu, s, o, 16);

        if (i < 12) {
            const float aw = e / s;
            const int l   = i >> 2;
            const int Dim = 128 >> l;                    // 128,64,32
            const int st  = (l == 0) ? 0 : (l == 1) ? 16384 : 20480;
            const float ref_x = refp_g[(size_t)bq * (NL * 2) + 2 * l];
            const float ref_y = refp_g[(size_t)bq * (NL * 2) + 2 * l + 1];
            const float ox = qproj_g[(size_t)bq * QS + h * 24 + 2 * i];
            const float oy = qproj_g[(size_t)bq * QS + h * 24 + 2 * i + 1];

            const float px = ref_x * (float)Dim + ox - 0.5f;
            const float py = ref_y * (float)Dim + oy - 0.5f;
            const float fx = floorf(px), fy = floorf(py);
            const float lx = px - fx, ly = py - fy;
            const int x0 = (int)fx, y0 = (int)fy;

            const bool vx0 = ((unsigned)x0       < (unsigned)Dim);
            const bool vx1 = ((unsigned)(x0 + 1) < (unsigned)Dim);
            const bool vy0 = ((unsigned)y0       < (unsigned)Dim);
            const bool vy1 = ((unsigned)(y0 + 1) < (unsigned)Dim);

            const int cx0 = min(max(x0, 0), Dim - 1);
            const int cx1 = min(max(x0 + 1, 0), Dim - 1);
            const int cy0 = min(max(y0, 0), Dim - 1);
            const int cy1 = min(max(y0 + 1, 0), Dim - 1);

            sp[i * 8 + 0] = (vx0 && vy0) ? aw * (1.f - lx) * (1.f - ly) : 0.f;
            sp[i * 8 + 1] = (vx1 && vy0) ? aw * lx * (1.f - ly) : 0.f;
            sp[i * 8 + 2] = (vx0 && vy1) ? aw * (1.f - lx) * ly : 0.f;
            sp[i * 8 + 3] = (vx1 && vy1) ? aw * lx * ly : 0.f;
            sp[i * 8 + 4] = __int_as_float((st + cy0 * Dim + cx0) * DM);
            sp[i * 8 + 5] = __int_as_float((st + cy0 * Dim + cx1) * DM);
            sp[i * 8 + 6] = __int_as_float((st + cy1 * Dim + cx0) * DM);
            sp[i * 8 + 7] = __int_as_float((st + cy1 * Dim + cx1) * DM);
        }
    }
    __syncwarp();

    // ---- phase 2: all lanes gather 12 points x 4 taps ----
    const float* vb = value_g + (size_t)b * SUMHW * DM + h * DH + lane;
    float a0 = 0.f, a1 = 0.f;
#pragma unroll
    for (int i = 0; i < 12; i++) {
        const float m00 = sp[i * 8 + 0];
        const float m10 = sp[i * 8 + 1];
        const float m01 = sp[i * 8 + 2];
        const float m11 = sp[i * 8 + 3];
        const int i00 = __float_as_int(sp[i * 8 + 4]);
        const int i10 = __float_as_int(sp[i * 8 + 5]);
        const int i01 = __float_as_int(sp[i * 8 + 6]);
        const int i11 = __float_as_int(sp[i * 8 + 7]);
        a0 = fmaf(m00, vb[i00], a0);
        a1 = fmaf(m10, vb[i10], a1);
        a0 = fmaf(m01, vb[i01], a0);
        a1 = fmaf(m11, vb[i11], a1);
    }
    acc_g[(size_t)bq * DM + h * DH + lane] = a0 + a1;
}

// ---------------- launch ---------------------------------------------------
extern "C" void kernel_launch(void* const* d_in, const int* in_sizes, int n_in,
                              void* d_out, int out_size)
{
    const float* query  = (const float*)d_in[0];
    const float* refpts = (const float*)d_in[1];
    const float* inflat = (const float*)d_in[2];
    const float* W_off  = (const float*)d_in[5];
    const float* b_off  = (const float*)d_in[6];
    const float* W_attn = (const float*)d_in[7];
    const float* b_attn = (const float*)d_in[8];
    const float* W_val  = (const float*)d_in[9];
    const float* b_val  = (const float*)d_in[10];
    const float* W_out  = (const float*)d_in[11];
    const float* b_out  = (const float*)d_in[12];
    float* out = (float*)d_out;

    float *value, *qproj, *acc, *wcat, *bcat;
    __half* wvalT;
    cudaGetSymbolAddress((void**)&value, g_value);
    cudaGetSymbolAddress((void**)&qproj, g_qproj);
    cudaGetSymbolAddress((void**)&acc,   g_acc);
    cudaGetSymbolAddress((void**)&wcat,  g_wcat);
    cudaGetSymbolAddress((void**)&bcat,  g_bcat);
    cudaGetSymbolAddress((void**)&wvalT, g_wvalT_h);

    const int MQ = BS * NQ;          // 7200
    const int MV = BS * SUMHW;       // 172032

    const int smem_g = 2 * 2 * 4096 * (int)sizeof(float);        // 64 KB
    const int smem_v = 3 * (AST + BST);                          // 73728 B
    cudaFuncSetAttribute(gemm_tf32_g,   cudaFuncAttributeMaxDynamicSharedMemorySize, smem_g);
    cudaFuncSetAttribute(gemm_f16_val4, cudaFuncAttributeMaxDynamicSharedMemorySize, smem_v);

    // 0) weight prep (tiny)
    concat_w<<<(DM * QS + 255) / 256, 256>>>(W_off, b_off, W_attn, b_attn, wcat, bcat);
    transpose_half<<<(DM * DM + 255) / 256, 256>>>(W_val, wvalT);

    // 1) fused q projection: [7200,256] @ [256,288] -> qproj (off | att)
    gemm_tf32_g<<<dim3(3, (MQ + 127) / 128), 256, smem_g>>>(
        query, wcat, bcat, qproj, MQ, QS, DM);

    // 2) value projection (fp16, warp 64x64, 3-stage): [172032,256] @ [256,256]
    gemm_f16_val4<<<MV / 128, 256, smem_v>>>(inflat, wvalT, b_val, value);

    // 3) sampling (lane-parallel precompute)
    {
        const int warps = BS * NQ * NH;
        const int blocks = (warps * 32 + 255) / 256;
        msda_sample2<<<blocks, 256>>>(refpts, qproj, value, acc);
    }

    // 4) output projection: [7200,256] @ [256,256] -> d_out
    gemm_tf32_g<<<dim3(2, (MQ + 127) / 128), 256, smem_g>>>(
        acc, W_out, b_out, out, MQ, DM, DM);
}